// round 1
// baseline (speedup 1.0000x reference)
#include <cuda_runtime.h>
#include <cstdint>

// Problem constants
#define BB 2
#define SS 2048
#define DD 1024
#define HH 16
#define HDD 64
#define MROWS (BB * SS)          // 4096
static constexpr float ATTN_SCALE = 1.0f / 32.0f;  // 1/sqrt(1024)

// ---------------------------------------------------------------------------
// Device scratch (no allocations allowed in kernel_launch)
// ---------------------------------------------------------------------------
__device__ float g_Q[BB * HH * SS * HDD];   // [B,H,S,HD]
__device__ float g_K[BB * HH * SS * HDD];
__device__ float g_V[BB * HH * SS * HDD];
__device__ float g_ctx[BB * SS * DD];       // [B,S,D]

// ---------------------------------------------------------------------------
// SGEMM: C[m,n] = sum_k A[m,k] * W[n,k]   (A: [4096,1024], W: [1024,1024])
// MODE 0: out[m*D + n] = C + bias[n]
// MODE 1: scatter to head layout g_X[((b*H+h)*S+s)*HD+hd], m=b*S+s, n=h*HD+hd
// Tiling: BM=BN=64, BK=16, 256 threads, 4x4 micro-tile per thread.
// ---------------------------------------------------------------------------
template <int MODE>
__global__ __launch_bounds__(256) void sgemm64(const float* __restrict__ A,
                                               const float* __restrict__ W,
                                               const float* __restrict__ bias,
                                               float* __restrict__ out) {
    constexpr int BM = 64, BN = 64, BK = 16;
    __shared__ __align__(16) float As[BK][BM];
    __shared__ __align__(16) float Bs[BK][BN];

    const int tid = threadIdx.x;
    const int bm = blockIdx.y * BM;
    const int bn = blockIdx.x * BN;
    const int tm = (tid / 16) * 4;   // 0..60
    const int tn = (tid % 16) * 4;   // 0..60

    // load mapping: each thread loads one float4 from A and one from W per tile
    const int lr = tid / 4;           // row in tile 0..63
    const int lc = (tid % 4) * 4;     // k offset 0,4,8,12
    const float* Aptr = A + (size_t)(bm + lr) * DD + lc;
    const float* Wptr = W + (size_t)(bn + lr) * DD + lc;

    float acc[4][4] = {};

    for (int k0 = 0; k0 < DD; k0 += BK) {
        float4 a4 = *reinterpret_cast<const float4*>(Aptr + k0);
        float4 w4 = *reinterpret_cast<const float4*>(Wptr + k0);
        __syncthreads();
        As[lc + 0][lr] = a4.x; As[lc + 1][lr] = a4.y;
        As[lc + 2][lr] = a4.z; As[lc + 3][lr] = a4.w;
        Bs[lc + 0][lr] = w4.x; Bs[lc + 1][lr] = w4.y;
        Bs[lc + 2][lr] = w4.z; Bs[lc + 3][lr] = w4.w;
        __syncthreads();

#pragma unroll
        for (int k = 0; k < BK; k++) {
            float4 av = *reinterpret_cast<const float4*>(&As[k][tm]);
            float4 bv = *reinterpret_cast<const float4*>(&Bs[k][tn]);
            float a[4] = {av.x, av.y, av.z, av.w};
            float b[4] = {bv.x, bv.y, bv.z, bv.w};
#pragma unroll
            for (int i = 0; i < 4; i++)
#pragma unroll
                for (int j = 0; j < 4; j++) acc[i][j] += a[i] * b[j];
        }
    }

    if (MODE == 0) {
#pragma unroll
        for (int i = 0; i < 4; i++) {
            const int m = bm + tm + i;
            float4 o;
            o.x = acc[i][0] + bias[bn + tn + 0];
            o.y = acc[i][1] + bias[bn + tn + 1];
            o.z = acc[i][2] + bias[bn + tn + 2];
            o.w = acc[i][3] + bias[bn + tn + 3];
            *reinterpret_cast<float4*>(out + (size_t)m * DD + bn + tn) = o;
        }
    } else {
#pragma unroll
        for (int i = 0; i < 4; i++) {
            const int m = bm + tm + i;
            const int b = m >> 11;          // m / S
            const int s = m & (SS - 1);     // m % S
#pragma unroll
            for (int j = 0; j < 4; j++) {
                const int n = bn + tn + j;
                const int h = n >> 6;       // n / HD
                const int hd = n & (HDD - 1);
                out[(((size_t)b * HH + h) * SS + s) * HDD + hd] = acc[i][j];
            }
        }
    }
}

// ---------------------------------------------------------------------------
// Flash attention (fp32): one q row per thread, 128 q rows per block.
// grid = (S/128, B*H), block = 128 threads.
// K/V staged per 64-key tile in SMEM (contiguous 16KB loads, broadcast reads).
// Online softmax; writes ctx in [B,S,D] layout for the Wo GEMM.
// ---------------------------------------------------------------------------
__global__ __launch_bounds__(128, 2) void attn_kernel() {
    const int t = threadIdx.x;
    const int bh = blockIdx.y;          // b*H + h
    const int q0 = blockIdx.x * 128;
    const int b = bh / HH;
    const int h = bh % HH;

    const float* Qp = g_Q + ((size_t)bh * SS + q0 + t) * HDD;
    const float* Kbase = g_K + (size_t)bh * SS * HDD;
    const float* Vbase = g_V + (size_t)bh * SS * HDD;

    float q[HDD];
#pragma unroll
    for (int d = 0; d < HDD; d++) q[d] = Qp[d] * ATTN_SCALE;

    float acc[HDD];
#pragma unroll
    for (int d = 0; d < HDD; d++) acc[d] = 0.0f;
    float mrun = -1e30f, lrun = 0.0f;

    __shared__ __align__(16) float Ks[64][64];
    __shared__ __align__(16) float Vs[64][64];

    for (int j0 = 0; j0 < SS; j0 += 64) {
        const float4* ksrc = reinterpret_cast<const float4*>(Kbase + (size_t)j0 * HDD);
        const float4* vsrc = reinterpret_cast<const float4*>(Vbase + (size_t)j0 * HDD);
        float4* kdst = reinterpret_cast<float4*>(&Ks[0][0]);
        float4* vdst = reinterpret_cast<float4*>(&Vs[0][0]);
        __syncthreads();
#pragma unroll
        for (int i = 0; i < 8; i++) {
            kdst[t + i * 128] = ksrc[t + i * 128];
            vdst[t + i * 128] = vsrc[t + i * 128];
        }
        __syncthreads();

        for (int j = 0; j < 64; j++) {
            float s0 = 0.f, s1 = 0.f, s2 = 0.f, s3 = 0.f;
#pragma unroll
            for (int d4 = 0; d4 < 16; d4++) {
                float4 k4 = *reinterpret_cast<const float4*>(&Ks[j][d4 * 4]);
                s0 += q[d4 * 4 + 0] * k4.x;
                s1 += q[d4 * 4 + 1] * k4.y;
                s2 += q[d4 * 4 + 2] * k4.z;
                s3 += q[d4 * 4 + 3] * k4.w;
            }
            const float s = (s0 + s1) + (s2 + s3);

            float p;
            if (s > mrun) {
                const float c = __expf(mrun - s);   // exp(-1e30-..) == 0 first time
                lrun *= c;
#pragma unroll
                for (int d = 0; d < HDD; d++) acc[d] *= c;
                mrun = s;
                p = 1.0f;
            } else {
                p = __expf(s - mrun);
            }
            lrun += p;
#pragma unroll
            for (int d4 = 0; d4 < 16; d4++) {
                float4 v4 = *reinterpret_cast<const float4*>(&Vs[j][d4 * 4]);
                acc[d4 * 4 + 0] += p * v4.x;
                acc[d4 * 4 + 1] += p * v4.y;
                acc[d4 * 4 + 2] += p * v4.z;
                acc[d4 * 4 + 3] += p * v4.w;
            }
        }
    }

    const float inv = 1.0f / lrun;
    float* outp = g_ctx + ((size_t)b * SS + q0 + t) * DD + h * HDD;
#pragma unroll
    for (int d4 = 0; d4 < 16; d4++) {
        float4 o;
        o.x = acc[d4 * 4 + 0] * inv;
        o.y = acc[d4 * 4 + 1] * inv;
        o.z = acc[d4 * 4 + 2] * inv;
        o.w = acc[d4 * 4 + 3] * inv;
        *reinterpret_cast<float4*>(outp + d4 * 4) = o;
    }
}

// ---------------------------------------------------------------------------
// Launch
// ---------------------------------------------------------------------------
extern "C" void kernel_launch(void* const* d_in, const int* in_sizes, int n_in,
                              void* d_out, int out_size) {
    const float* query = (const float*)d_in[0];
    const float* key_i = (const float*)d_in[1];
    const float* value = (const float*)d_in[2];
    const float* Wq = (const float*)d_in[3];
    const float* Wk = (const float*)d_in[4];
    const float* Wv = (const float*)d_in[5];
    const float* Wo = (const float*)d_in[6];
    const float* bo = (const float*)d_in[7];
    float* out = (float*)d_out;

    float *qg, *kg, *vg, *ctxg;
    cudaGetSymbolAddress((void**)&qg, g_Q);
    cudaGetSymbolAddress((void**)&kg, g_K);
    cudaGetSymbolAddress((void**)&vg, g_V);
    cudaGetSymbolAddress((void**)&ctxg, g_ctx);

    dim3 gblk(256);
    dim3 ggrid(DD / 64, MROWS / 64);  // (16, 64)

    // Projections -> head-layout Q/K/V
    sgemm64<1><<<ggrid, gblk>>>(query, Wq, nullptr, qg);
    sgemm64<1><<<ggrid, gblk>>>(key_i, Wk, nullptr, kg);
    sgemm64<1><<<ggrid, gblk>>>(value, Wv, nullptr, vg);

    // Attention -> ctx [B,S,D]
    dim3 ablk(128);
    dim3 agrid(SS / 128, BB * HH);    // (16, 32)
    attn_kernel<<<agrid, ablk>>>();

    // Output projection with bias
    sgemm64<0><<<ggrid, gblk>>>(ctxg, Wo, bo, out);
}

// round 3
// speedup vs baseline: 1.3252x; 1.3252x over previous
#include <cuda_runtime.h>
#include <cuda_bf16.h>
#include <cstdint>

// Problem constants
#define BB 2
#define SS 2048
#define DD 1024
#define HH 16
#define HDD 64
#define MROWS (BB * SS)          // 4096
#define KS (3 * DD)              // 3072 (bf16 3-term split)
static constexpr float ATTN_SCALE = 1.0f / 32.0f;  // 1/sqrt(1024)

// ---------------------------------------------------------------------------
// Device scratch
// ---------------------------------------------------------------------------
__device__ float g_Q[BB * HH * SS * HDD];   // [B,H,S,HD]
__device__ float g_K[BB * HH * SS * HDD];
__device__ float g_V[BB * HH * SS * HDD];
__device__ float g_ctx[MROWS * DD];         // [B,S,D]
__device__ __nv_bfloat16 g_A2[(size_t)MROWS * KS];  // 24 MB split activations
__device__ __nv_bfloat16 g_B2[(size_t)DD * KS];     //  6 MB split weights

// ---------------------------------------------------------------------------
// Helpers (baseline PTX only: cp.async / ldmatrix / mma.sync)
// ---------------------------------------------------------------------------
__device__ __forceinline__ uint32_t smem_u32(const void* p) {
    uint32_t a;
    asm("{ .reg .u64 t; cvta.to.shared.u64 t, %1; cvt.u32.u64 %0, t; }" : "=r"(a) : "l"(p));
    return a;
}
__device__ __forceinline__ void cp16(uint32_t s, const void* g) {
    asm volatile("cp.async.cg.shared.global [%0], [%1], 16;" :: "r"(s), "l"(g));
}
__device__ __forceinline__ void cp_commit() {
    asm volatile("cp.async.commit_group;" ::: "memory");
}
template <int N>
__device__ __forceinline__ void cp_wait() {
    asm volatile("cp.async.wait_group %0;" :: "n"(N) : "memory");
}
__device__ __forceinline__ void ldm_x4(uint32_t* r, uint32_t addr) {
    asm volatile("ldmatrix.sync.aligned.m8n8.x4.shared.b16 {%0,%1,%2,%3}, [%4];"
                 : "=r"(r[0]), "=r"(r[1]), "=r"(r[2]), "=r"(r[3]) : "r"(addr));
}
__device__ __forceinline__ void mma16816(float* d, const uint32_t* a, const uint32_t* b) {
    asm volatile(
        "mma.sync.aligned.m16n8k16.row.col.f32.bf16.bf16.f32 "
        "{%0,%1,%2,%3}, {%4,%5,%6,%7}, {%8,%9}, {%0,%1,%2,%3};"
        : "+f"(d[0]), "+f"(d[1]), "+f"(d[2]), "+f"(d[3])
        : "r"(a[0]), "r"(a[1]), "r"(a[2]), "r"(a[3]), "r"(b[0]), "r"(b[1]));
}

// ---------------------------------------------------------------------------
// fp32 -> bf16 hi/lo split with K-packing.
// A-side (BSIDE=0): segments [hi | hi | lo]; B-side (BSIDE=1): [hi | lo | hi]
// dropped term: lo_A*lo_B ~ 2^-18 relative.
// ---------------------------------------------------------------------------
template <int BSIDE>
__global__ __launch_bounds__(256) void conv_split(const float* __restrict__ in,
                                                  __nv_bfloat16* __restrict__ out,
                                                  int rows) {
    int idx = blockIdx.x * 256 + threadIdx.x;   // float2 index
    int total = rows * (DD / 2);
    if (idx >= total) return;
    int r = idx / (DD / 2);
    int c2 = idx - r * (DD / 2);
    float2 x = reinterpret_cast<const float2*>(in)[(size_t)r * (DD / 2) + c2];
    __nv_bfloat16 h0 = __float2bfloat16(x.x);
    __nv_bfloat16 h1 = __float2bfloat16(x.y);
    __nv_bfloat16 l0 = __float2bfloat16(x.x - __bfloat162float(h0));
    __nv_bfloat16 l1 = __float2bfloat16(x.y - __bfloat162float(h1));
    __nv_bfloat162 hi; hi.x = h0; hi.y = h1;
    __nv_bfloat162 lo; lo.x = l0; lo.y = l1;
    __nv_bfloat162* o = reinterpret_cast<__nv_bfloat162*>(out) + (size_t)r * (KS / 2) + c2;
    if (BSIDE) { o[0] = hi; o[DD / 2] = lo; o[DD] = hi; }
    else       { o[0] = hi; o[DD / 2] = hi; o[DD] = lo; }
}

// ---------------------------------------------------------------------------
// bf16 tensor-core GEMM via mma.sync: C[m,n] = sum_k A2[m,k]*B2[n,k]
// CTA 128x128, BK=32, 256 threads (8 warps: 2x4), warp tile 64x32.
// cp.async double buffer; SMEM rows padded to 80B (conflict-free ldmatrix).
// MODE 0: out[m*DD+n] = C + bias[n]
// MODE 1: scatter to head layout g_X[((b*H+h)*S+s)*HD+hd]
// ---------------------------------------------------------------------------
#define LDHW 40   // smem row stride in halfwords (80 bytes)

template <int MODE>
__global__ __launch_bounds__(256) void gemm_mma(const __nv_bfloat16* __restrict__ A2,
                                                const __nv_bfloat16* __restrict__ B2,
                                                const float* __restrict__ bias,
                                                float* __restrict__ out) {
    constexpr int NK = KS / 32;   // 96
    __shared__ __align__(16) __nv_bfloat16 sA[2][128 * LDHW];
    __shared__ __align__(16) __nv_bfloat16 sB[2][128 * LDHW];

    const int t = threadIdx.x;
    const int lane = t & 31;
    const int wid = t >> 5;
    const int wm = (wid >> 2) * 64;   // warp M offset: 0 or 64
    const int wn = (wid & 3) * 32;    // warp N offset: 0,32,64,96
    const int bm = blockIdx.y * 128;
    const int bn = blockIdx.x * 128;

    const uint32_t sAb[2] = { smem_u32(&sA[0][0]), smem_u32(&sA[1][0]) };
    const uint32_t sBb[2] = { smem_u32(&sB[0][0]), smem_u32(&sB[1][0]) };

    // global->smem mapping: row = t>>1 (0..127), seg = t&1 (two 16B chunks)
    const int grow = t >> 1;
    const int gseg = t & 1;
    const __nv_bfloat16* Ag = A2 + (size_t)(bm + grow) * KS + gseg * 16;
    const __nv_bfloat16* Bg = B2 + (size_t)(bn + grow) * KS + gseg * 16;
    const uint32_t soff = (uint32_t)grow * (LDHW * 2) + gseg * 32;  // bytes

    auto load_tile = [&](int buf, int kt) {
        const int k0 = kt * 32;
        cp16(sAb[buf] + soff,      Ag + k0);
        cp16(sAb[buf] + soff + 16, Ag + k0 + 8);
        cp16(sBb[buf] + soff,      Bg + k0);
        cp16(sBb[buf] + soff + 16, Bg + k0 + 8);
        cp_commit();
    };

    // ldmatrix source addresses (byte offsets into tile)
    // A: matrix row = m, col = k. lanes 0-15 rows, lanes 16-31 k+8.
    const uint32_t aoff = (uint32_t)(wm + (lane & 15)) * (LDHW * 2) + ((lane >> 4) << 4);
    // B: matrix row = n, col = k.
    const uint32_t boff = (uint32_t)(wn + (lane & 7) + ((lane >> 4) << 3)) * (LDHW * 2)
                        + (((lane >> 3) & 1) << 4);

    float d[4][4][4];
#pragma unroll
    for (int i = 0; i < 4; i++)
#pragma unroll
        for (int j = 0; j < 4; j++)
#pragma unroll
            for (int r = 0; r < 4; r++) d[i][j][r] = 0.0f;

    load_tile(0, 0);
    int cur = 0;
    for (int kt = 0; kt < NK; ++kt) {
        if (kt + 1 < NK) load_tile(cur ^ 1, kt + 1);
        if (kt + 1 < NK) cp_wait<1>(); else cp_wait<0>();
        __syncthreads();

        uint32_t a[4][2][4];
        uint32_t b[4][2][2];
#pragma unroll
        for (int mf = 0; mf < 4; mf++)
#pragma unroll
            for (int kf = 0; kf < 2; kf++)
                ldm_x4(a[mf][kf], sAb[cur] + aoff + mf * 16 * (LDHW * 2) + kf * 32);
#pragma unroll
        for (int nf2 = 0; nf2 < 2; nf2++)
#pragma unroll
            for (int kf = 0; kf < 2; kf++) {
                uint32_t r[4];
                ldm_x4(r, sBb[cur] + boff + nf2 * 16 * (LDHW * 2) + kf * 32);
                b[nf2 * 2 + 0][kf][0] = r[0]; b[nf2 * 2 + 0][kf][1] = r[1];
                b[nf2 * 2 + 1][kf][0] = r[2]; b[nf2 * 2 + 1][kf][1] = r[3];
            }
#pragma unroll
        for (int mf = 0; mf < 4; mf++)
#pragma unroll
            for (int nf = 0; nf < 4; nf++) {
                mma16816(d[mf][nf], a[mf][0], b[nf][0]);
                mma16816(d[mf][nf], a[mf][1], b[nf][1]);
            }
        __syncthreads();
        cur ^= 1;
    }

    // Epilogue: lane owns rows (l>>2, l>>2+8), cols (l&3)*2,+1 per 16x8 frag
    const int mrow = bm + wm + (lane >> 2);
    const int ncol0 = bn + wn + (lane & 3) * 2;
#pragma unroll
    for (int mf = 0; mf < 4; mf++) {
#pragma unroll
        for (int half = 0; half < 2; half++) {
            const int m = mrow + mf * 16 + half * 8;
            if (MODE == 0) {
                float* orow = out + (size_t)m * DD;
#pragma unroll
                for (int nf = 0; nf < 4; nf++) {
                    const int n = ncol0 + nf * 8;
                    float2 o;
                    o.x = d[mf][nf][half * 2 + 0] + bias[n];
                    o.y = d[mf][nf][half * 2 + 1] + bias[n + 1];
                    *reinterpret_cast<float2*>(orow + n) = o;
                }
            } else {
                const int b = m >> 11;
                const int s = m & (SS - 1);
                float* obase = out + ((size_t)b * HH * SS + s) * HDD;
#pragma unroll
                for (int nf = 0; nf < 4; nf++) {
                    const int n = ncol0 + nf * 8;
                    const int h = n >> 6;
                    const int hd = n & (HDD - 1);
                    float2 o;
                    o.x = d[mf][nf][half * 2 + 0];
                    o.y = d[mf][nf][half * 2 + 1];
                    *reinterpret_cast<float2*>(obase + (size_t)h * SS * HDD + hd) = o;
                }
            }
        }
    }
}

// ---------------------------------------------------------------------------
// Flash attention (fp32) — unchanged
// ---------------------------------------------------------------------------
__global__ __launch_bounds__(128, 2) void attn_kernel() {
    const int t = threadIdx.x;
    const int bh = blockIdx.y;
    const int q0 = blockIdx.x * 128;
    const int b = bh / HH;
    const int h = bh % HH;

    const float* Qp = g_Q + ((size_t)bh * SS + q0 + t) * HDD;
    const float* Kbase = g_K + (size_t)bh * SS * HDD;
    const float* Vbase = g_V + (size_t)bh * SS * HDD;

    float q[HDD];
#pragma unroll
    for (int d = 0; d < HDD; d++) q[d] = Qp[d] * ATTN_SCALE;

    float acc[HDD];
#pragma unroll
    for (int d = 0; d < HDD; d++) acc[d] = 0.0f;
    float mrun = -1e30f, lrun = 0.0f;

    __shared__ __align__(16) float Ks[64][64];
    __shared__ __align__(16) float Vs[64][64];

    for (int j0 = 0; j0 < SS; j0 += 64) {
        const float4* ksrc = reinterpret_cast<const float4*>(Kbase + (size_t)j0 * HDD);
        const float4* vsrc = reinterpret_cast<const float4*>(Vbase + (size_t)j0 * HDD);
        float4* kdst = reinterpret_cast<float4*>(&Ks[0][0]);
        float4* vdst = reinterpret_cast<float4*>(&Vs[0][0]);
        __syncthreads();
#pragma unroll
        for (int i = 0; i < 8; i++) {
            kdst[t + i * 128] = ksrc[t + i * 128];
            vdst[t + i * 128] = vsrc[t + i * 128];
        }
        __syncthreads();

        for (int j = 0; j < 64; j++) {
            float s0 = 0.f, s1 = 0.f, s2 = 0.f, s3 = 0.f;
#pragma unroll
            for (int d4 = 0; d4 < 16; d4++) {
                float4 k4 = *reinterpret_cast<const float4*>(&Ks[j][d4 * 4]);
                s0 += q[d4 * 4 + 0] * k4.x;
                s1 += q[d4 * 4 + 1] * k4.y;
                s2 += q[d4 * 4 + 2] * k4.z;
                s3 += q[d4 * 4 + 3] * k4.w;
            }
            const float s = (s0 + s1) + (s2 + s3);

            float p;
            if (s > mrun) {
                const float c = __expf(mrun - s);
                lrun *= c;
#pragma unroll
                for (int d = 0; d < HDD; d++) acc[d] *= c;
                mrun = s;
                p = 1.0f;
            } else {
                p = __expf(s - mrun);
            }
            lrun += p;
#pragma unroll
            for (int d4 = 0; d4 < 16; d4++) {
                float4 v4 = *reinterpret_cast<const float4*>(&Vs[j][d4 * 4]);
                acc[d4 * 4 + 0] += p * v4.x;
                acc[d4 * 4 + 1] += p * v4.y;
                acc[d4 * 4 + 2] += p * v4.z;
                acc[d4 * 4 + 3] += p * v4.w;
            }
        }
    }

    const float inv = 1.0f / lrun;
    float* outp = g_ctx + ((size_t)b * SS + q0 + t) * DD + h * HDD;
#pragma unroll
    for (int d4 = 0; d4 < 16; d4++) {
        float4 o;
        o.x = acc[d4 * 4 + 0] * inv;
        o.y = acc[d4 * 4 + 1] * inv;
        o.z = acc[d4 * 4 + 2] * inv;
        o.w = acc[d4 * 4 + 3] * inv;
        *reinterpret_cast<float4*>(outp + d4 * 4) = o;
    }
}

// ---------------------------------------------------------------------------
// Launch
// ---------------------------------------------------------------------------
extern "C" void kernel_launch(void* const* d_in, const int* in_sizes, int n_in,
                              void* d_out, int out_size) {
    const float* query = (const float*)d_in[0];
    const float* key_i = (const float*)d_in[1];
    const float* value = (const float*)d_in[2];
    const float* Wq = (const float*)d_in[3];
    const float* Wk = (const float*)d_in[4];
    const float* Wv = (const float*)d_in[5];
    const float* Wo = (const float*)d_in[6];
    const float* bo = (const float*)d_in[7];
    float* out = (float*)d_out;

    float *qg, *kg, *vg, *ctxg;
    __nv_bfloat16 *a2, *b2;
    cudaGetSymbolAddress((void**)&qg, g_Q);
    cudaGetSymbolAddress((void**)&kg, g_K);
    cudaGetSymbolAddress((void**)&vg, g_V);
    cudaGetSymbolAddress((void**)&ctxg, g_ctx);
    cudaGetSymbolAddress((void**)&a2, g_A2);
    cudaGetSymbolAddress((void**)&b2, g_B2);

    dim3 ggrid(DD / 128, MROWS / 128);      // (8, 32)
    const int CONV_A_BLOCKS = (MROWS * DD / 2 + 255) / 256;  // 8192
    const int CONV_W_BLOCKS = (DD * DD / 2 + 255) / 256;     // 2048

    // Q = query @ Wq^T  (scatter to head layout)
    conv_split<0><<<CONV_A_BLOCKS, 256>>>(query, a2, MROWS);
    conv_split<1><<<CONV_W_BLOCKS, 256>>>(Wq, b2, DD);
    gemm_mma<1><<<ggrid, 256>>>(a2, b2, nullptr, qg);

    // K
    conv_split<0><<<CONV_A_BLOCKS, 256>>>(key_i, a2, MROWS);
    conv_split<1><<<CONV_W_BLOCKS, 256>>>(Wk, b2, DD);
    gemm_mma<1><<<ggrid, 256>>>(a2, b2, nullptr, kg);

    // V
    conv_split<0><<<CONV_A_BLOCKS, 256>>>(value, a2, MROWS);
    conv_split<1><<<CONV_W_BLOCKS, 256>>>(Wv, b2, DD);
    gemm_mma<1><<<ggrid, 256>>>(a2, b2, nullptr, vg);

    // Attention -> ctx [B,S,D]
    dim3 ablk(128);
    dim3 agrid(SS / 128, BB * HH);
    attn_kernel<<<agrid, ablk>>>();

    // Output projection with bias
    conv_split<0><<<CONV_A_BLOCKS, 256>>>(ctxg, a2, MROWS);
    conv_split<1><<<CONV_W_BLOCKS, 256>>>(Wo, b2, DD);
    gemm_mma<0><<<ggrid, 256>>>(a2, b2, bo, out);
}

// round 4
// speedup vs baseline: 2.8452x; 2.1469x over previous
#include <cuda_runtime.h>
#include <cuda_bf16.h>
#include <cstdint>

// Problem constants
#define BB 2
#define SS 2048
#define DD 1024
#define HH 16
#define HDD 64
#define MROWS (BB * SS)          // 4096
#define KS (3 * DD)              // 3072 (bf16 3-term split for GEMMs)
static constexpr float QMULT = 1.4426950408889634f / 32.0f;  // log2(e)/sqrt(D)

// ---------------------------------------------------------------------------
// Device scratch
// ---------------------------------------------------------------------------
__device__ __nv_bfloat16 g_Qs[(size_t)BB * HH * SS * 128];  // [BH,S,hi64|lo64]
__device__ __nv_bfloat16 g_Ks[(size_t)BB * HH * SS * 128];
__device__ __nv_bfloat16 g_Vs[(size_t)BB * HH * SS * 128];
__device__ float g_ctx[MROWS * DD];                          // [B,S,D]
__device__ __nv_bfloat16 g_A2[(size_t)MROWS * KS];
__device__ __nv_bfloat16 g_B2[(size_t)DD * KS];

// ---------------------------------------------------------------------------
// Helpers (baseline PTX only: cp.async / ldmatrix / mma.sync)
// ---------------------------------------------------------------------------
__device__ __forceinline__ uint32_t smem_u32(const void* p) {
    uint32_t a;
    asm("{ .reg .u64 t; cvta.to.shared.u64 t, %1; cvt.u32.u64 %0, t; }" : "=r"(a) : "l"(p));
    return a;
}
__device__ __forceinline__ void cp16(uint32_t s, const void* g) {
    asm volatile("cp.async.cg.shared.global [%0], [%1], 16;" :: "r"(s), "l"(g));
}
__device__ __forceinline__ void cp_commit() {
    asm volatile("cp.async.commit_group;" ::: "memory");
}
template <int N>
__device__ __forceinline__ void cp_wait() {
    asm volatile("cp.async.wait_group %0;" :: "n"(N) : "memory");
}
__device__ __forceinline__ void ldm_x4(uint32_t* r, uint32_t addr) {
    asm volatile("ldmatrix.sync.aligned.m8n8.x4.shared.b16 {%0,%1,%2,%3}, [%4];"
                 : "=r"(r[0]), "=r"(r[1]), "=r"(r[2]), "=r"(r[3]) : "r"(addr));
}
__device__ __forceinline__ void ldm_x4_t(uint32_t* r, uint32_t addr) {
    asm volatile("ldmatrix.sync.aligned.m8n8.x4.trans.shared.b16 {%0,%1,%2,%3}, [%4];"
                 : "=r"(r[0]), "=r"(r[1]), "=r"(r[2]), "=r"(r[3]) : "r"(addr));
}
__device__ __forceinline__ void mma16816(float* d, const uint32_t* a, const uint32_t* b) {
    asm volatile(
        "mma.sync.aligned.m16n8k16.row.col.f32.bf16.bf16.f32 "
        "{%0,%1,%2,%3}, {%4,%5,%6,%7}, {%8,%9}, {%0,%1,%2,%3};"
        : "+f"(d[0]), "+f"(d[1]), "+f"(d[2]), "+f"(d[3])
        : "r"(a[0]), "r"(a[1]), "r"(a[2]), "r"(a[3]), "r"(b[0]), "r"(b[1]));
}
__device__ __forceinline__ float ex2f(float x) {
    float r;
    asm("ex2.approx.ftz.f32 %0, %1;" : "=f"(r) : "f"(x));
    return r;
}
__device__ __forceinline__ void split_pack(float x, float y, uint32_t& hi, uint32_t& lo) {
    __nv_bfloat16 hx = __float2bfloat16(x);
    __nv_bfloat16 hy = __float2bfloat16(y);
    __nv_bfloat16 lx = __float2bfloat16(x - __bfloat162float(hx));
    __nv_bfloat16 ly = __float2bfloat16(y - __bfloat162float(hy));
    __nv_bfloat162 h2; h2.x = hx; h2.y = hy;
    __nv_bfloat162 l2; l2.x = lx; l2.y = ly;
    hi = *reinterpret_cast<uint32_t*>(&h2);
    lo = *reinterpret_cast<uint32_t*>(&l2);
}

// ---------------------------------------------------------------------------
// fp32 -> bf16 hi/lo split with K-packing (for dense GEMMs).
// A-side (BSIDE=0): [hi | hi | lo]; B-side (BSIDE=1): [hi | lo | hi]
// ---------------------------------------------------------------------------
template <int BSIDE>
__global__ __launch_bounds__(256) void conv_split(const float* __restrict__ in,
                                                  __nv_bfloat16* __restrict__ out,
                                                  int rows) {
    int idx = blockIdx.x * 256 + threadIdx.x;
    int total = rows * (DD / 2);
    if (idx >= total) return;
    int r = idx / (DD / 2);
    int c2 = idx - r * (DD / 2);
    float2 x = reinterpret_cast<const float2*>(in)[(size_t)r * (DD / 2) + c2];
    __nv_bfloat16 h0 = __float2bfloat16(x.x);
    __nv_bfloat16 h1 = __float2bfloat16(x.y);
    __nv_bfloat16 l0 = __float2bfloat16(x.x - __bfloat162float(h0));
    __nv_bfloat16 l1 = __float2bfloat16(x.y - __bfloat162float(h1));
    __nv_bfloat162 hi; hi.x = h0; hi.y = h1;
    __nv_bfloat162 lo; lo.x = l0; lo.y = l1;
    __nv_bfloat162* o = reinterpret_cast<__nv_bfloat162*>(out) + (size_t)r * (KS / 2) + c2;
    if (BSIDE) { o[0] = hi; o[DD / 2] = lo; o[DD] = hi; }
    else       { o[0] = hi; o[DD / 2] = hi; o[DD] = lo; }
}

// ---------------------------------------------------------------------------
// bf16 tensor-core GEMM: C[m,n] = sum_k A2[m,k]*B2[n,k]
// MODE 0: float out[m*DD+n] = C + bias[n]
// MODE 2: Q split: bf16 out[((b*H+h)*S+s)*128 + hd] = hi(C*QMULT), +64 = lo
// MODE 3: K/V split: same layout, mult=1
// ---------------------------------------------------------------------------
#define LDHW 40   // smem row stride in halfwords (80 bytes)

template <int MODE>
__global__ __launch_bounds__(256) void gemm_mma(const __nv_bfloat16* __restrict__ A2,
                                                const __nv_bfloat16* __restrict__ B2,
                                                const float* __restrict__ bias,
                                                void* __restrict__ outv) {
    constexpr int NK = KS / 32;   // 96
    __shared__ __align__(16) __nv_bfloat16 sA[2][128 * LDHW];
    __shared__ __align__(16) __nv_bfloat16 sB[2][128 * LDHW];

    const int t = threadIdx.x;
    const int lane = t & 31;
    const int wid = t >> 5;
    const int wm = (wid >> 2) * 64;
    const int wn = (wid & 3) * 32;
    const int bm = blockIdx.y * 128;
    const int bn = blockIdx.x * 128;

    const uint32_t sAb[2] = { smem_u32(&sA[0][0]), smem_u32(&sA[1][0]) };
    const uint32_t sBb[2] = { smem_u32(&sB[0][0]), smem_u32(&sB[1][0]) };

    const int grow = t >> 1;
    const int gseg = t & 1;
    const __nv_bfloat16* Ag = A2 + (size_t)(bm + grow) * KS + gseg * 16;
    const __nv_bfloat16* Bg = B2 + (size_t)(bn + grow) * KS + gseg * 16;
    const uint32_t soff = (uint32_t)grow * (LDHW * 2) + gseg * 32;

    auto load_tile = [&](int buf, int kt) {
        const int k0 = kt * 32;
        cp16(sAb[buf] + soff,      Ag + k0);
        cp16(sAb[buf] + soff + 16, Ag + k0 + 8);
        cp16(sBb[buf] + soff,      Bg + k0);
        cp16(sBb[buf] + soff + 16, Bg + k0 + 8);
        cp_commit();
    };

    const uint32_t aoff = (uint32_t)(wm + (lane & 15)) * (LDHW * 2) + ((lane >> 4) << 4);
    const uint32_t boff = (uint32_t)(wn + (lane & 7) + ((lane >> 4) << 3)) * (LDHW * 2)
                        + (((lane >> 3) & 1) << 4);

    float d[4][4][4];
#pragma unroll
    for (int i = 0; i < 4; i++)
#pragma unroll
        for (int j = 0; j < 4; j++)
#pragma unroll
            for (int r = 0; r < 4; r++) d[i][j][r] = 0.0f;

    load_tile(0, 0);
    int cur = 0;
    for (int kt = 0; kt < NK; ++kt) {
        if (kt + 1 < NK) load_tile(cur ^ 1, kt + 1);
        if (kt + 1 < NK) cp_wait<1>(); else cp_wait<0>();
        __syncthreads();

        uint32_t a[4][2][4];
        uint32_t b[4][2][2];
#pragma unroll
        for (int mf = 0; mf < 4; mf++)
#pragma unroll
            for (int kf = 0; kf < 2; kf++)
                ldm_x4(a[mf][kf], sAb[cur] + aoff + mf * 16 * (LDHW * 2) + kf * 32);
#pragma unroll
        for (int nf2 = 0; nf2 < 2; nf2++)
#pragma unroll
            for (int kf = 0; kf < 2; kf++) {
                uint32_t r[4];
                ldm_x4(r, sBb[cur] + boff + nf2 * 16 * (LDHW * 2) + kf * 32);
                b[nf2 * 2 + 0][kf][0] = r[0]; b[nf2 * 2 + 0][kf][1] = r[1];
                b[nf2 * 2 + 1][kf][0] = r[2]; b[nf2 * 2 + 1][kf][1] = r[3];
            }
#pragma unroll
        for (int mf = 0; mf < 4; mf++)
#pragma unroll
            for (int nf = 0; nf < 4; nf++) {
                mma16816(d[mf][nf], a[mf][0], b[nf][0]);
                mma16816(d[mf][nf], a[mf][1], b[nf][1]);
            }
        __syncthreads();
        cur ^= 1;
    }

    const int mrow = bm + wm + (lane >> 2);
    const int ncol0 = bn + wn + (lane & 3) * 2;
#pragma unroll
    for (int mf = 0; mf < 4; mf++) {
#pragma unroll
        for (int half = 0; half < 2; half++) {
            const int m = mrow + mf * 16 + half * 8;
            if (MODE == 0) {
                float* out = (float*)outv;
                float* orow = out + (size_t)m * DD;
#pragma unroll
                for (int nf = 0; nf < 4; nf++) {
                    const int n = ncol0 + nf * 8;
                    float2 o;
                    o.x = d[mf][nf][half * 2 + 0] + bias[n];
                    o.y = d[mf][nf][half * 2 + 1] + bias[n + 1];
                    *reinterpret_cast<float2*>(orow + n) = o;
                }
            } else {
                __nv_bfloat16* out = (__nv_bfloat16*)outv;
                const float mult = (MODE == 2) ? QMULT : 1.0f;
                const int b = m >> 11;
                const int s = m & (SS - 1);
#pragma unroll
                for (int nf = 0; nf < 4; nf++) {
                    const int n = ncol0 + nf * 8;
                    const int h = n >> 6;
                    const int hd = n & (HDD - 1);
                    __nv_bfloat16* base =
                        out + (((size_t)b * HH + h) * SS + s) * 128 + hd;
                    uint32_t hi, lo;
                    split_pack(d[mf][nf][half * 2 + 0] * mult,
                               d[mf][nf][half * 2 + 1] * mult, hi, lo);
                    *reinterpret_cast<uint32_t*>(base) = hi;
                    *reinterpret_cast<uint32_t*>(base + 64) = lo;
                }
            }
        }
    }
}

// ---------------------------------------------------------------------------
// Tensor-core flash attention.
// grid (S/128, B*H), 256 threads (8 warps x 16 q rows).
// Q/K/V pre-split bf16 [S, hi64|lo64]. 64-key tiles.
// QK^T and PV each via 3-term bf16 split; online softmax in registers.
// ---------------------------------------------------------------------------
#define LDA 136   // attn smem row stride in halfwords (272B)

__global__ __launch_bounds__(256) void attn_mma() {
    __shared__ __align__(16) __nv_bfloat16 smem[128 * LDA];  // 34,816 B

    const int t = threadIdx.x;
    const int lane = t & 31;
    const int w = t >> 5;
    const int bh = blockIdx.y;
    const int q0 = blockIdx.x * 128;

    const uint32_t sbase = smem_u32(smem);
    const uint32_t sK = sbase;
    const uint32_t sV = sbase + 64 * (LDA * 2);

    // ---- stage Q tile (128 rows x 256B), load A-fragments, free the smem ----
    const __nv_bfloat16* Qg = g_Qs + ((size_t)bh * SS + q0) * 128;
#pragma unroll
    for (int i = 0; i < 8; i++) {
        int idx = i * 256 + t;
        int row = idx >> 4, ch = idx & 15;
        cp16(sbase + row * (LDA * 2) + ch * 16, Qg + (size_t)row * 128 + ch * 8);
    }
    cp_commit(); cp_wait<0>();
    __syncthreads();

    uint32_t qa[2][4][4];   // [hi/lo][kf][reg]
    const uint32_t aoff = (uint32_t)(w * 16 + (lane & 15)) * (LDA * 2) + ((lane >> 4) << 4);
#pragma unroll
    for (int kf = 0; kf < 4; kf++) {
        ldm_x4(qa[0][kf], sbase + aoff + kf * 32);
        ldm_x4(qa[1][kf], sbase + aoff + 128 + kf * 32);
    }
    __syncthreads();

    // ---- state ----
    float o[8][4];
#pragma unroll
    for (int f = 0; f < 8; f++)
#pragma unroll
        for (int r = 0; r < 4; r++) o[f][r] = 0.0f;
    float mrow[2] = { -1e30f, -1e30f };
    float lsum[2] = { 0.0f, 0.0f };

    const __nv_bfloat16* Kg = g_Ks + (size_t)bh * SS * 128;
    const __nv_bfloat16* Vg = g_Vs + (size_t)bh * SS * 128;

    const uint32_t boff = (uint32_t)((lane & 7) + ((lane >> 4) << 3)) * (LDA * 2)
                        + (((lane >> 3) & 1) << 4);
    const uint32_t voff = (uint32_t)(lane & 15) * (LDA * 2) + ((lane >> 4) << 4);

    for (int k0 = 0; k0 < SS; k0 += 64) {
        // load K,V tiles
#pragma unroll
        for (int i = 0; i < 4; i++) {
            int idx = i * 256 + t;
            int row = idx >> 4, ch = idx & 15;
            cp16(sK + row * (LDA * 2) + ch * 16, Kg + ((size_t)(k0 + row)) * 128 + ch * 8);
            cp16(sV + row * (LDA * 2) + ch * 16, Vg + ((size_t)(k0 + row)) * 128 + ch * 8);
        }
        cp_commit(); cp_wait<0>();
        __syncthreads();

        // ---- S = Q K^T (3-term split), S already in log2 domain ----
        float s[8][4];
#pragma unroll
        for (int f = 0; f < 8; f++)
#pragma unroll
            for (int r = 0; r < 4; r++) s[f][r] = 0.0f;
#pragma unroll
        for (int kf = 0; kf < 4; kf++) {
#pragma unroll
            for (int nc = 0; nc < 4; nc++) {
                uint32_t bhh[4], bll[4];
                ldm_x4(bhh, sK + boff + nc * 16 * (LDA * 2) + kf * 32);
                ldm_x4(bll, sK + boff + nc * 16 * (LDA * 2) + 128 + kf * 32);
                mma16816(s[2 * nc],     qa[0][kf], bhh + 0);
                mma16816(s[2 * nc + 1], qa[0][kf], bhh + 2);
                mma16816(s[2 * nc],     qa[1][kf], bhh + 0);
                mma16816(s[2 * nc + 1], qa[1][kf], bhh + 2);
                mma16816(s[2 * nc],     qa[0][kf], bll + 0);
                mma16816(s[2 * nc + 1], qa[0][kf], bll + 2);
            }
        }

        // ---- online softmax ----
        float tm0 = -1e30f, tm1 = -1e30f;
#pragma unroll
        for (int f = 0; f < 8; f++) {
            tm0 = fmaxf(tm0, fmaxf(s[f][0], s[f][1]));
            tm1 = fmaxf(tm1, fmaxf(s[f][2], s[f][3]));
        }
        tm0 = fmaxf(tm0, __shfl_xor_sync(0xffffffffu, tm0, 1));
        tm0 = fmaxf(tm0, __shfl_xor_sync(0xffffffffu, tm0, 2));
        tm1 = fmaxf(tm1, __shfl_xor_sync(0xffffffffu, tm1, 1));
        tm1 = fmaxf(tm1, __shfl_xor_sync(0xffffffffu, tm1, 2));
        const float mn0 = fmaxf(mrow[0], tm0);
        const float mn1 = fmaxf(mrow[1], tm1);
        const float sc0 = ex2f(mrow[0] - mn0);
        const float sc1 = ex2f(mrow[1] - mn1);
        mrow[0] = mn0; mrow[1] = mn1;
        lsum[0] *= sc0; lsum[1] *= sc1;
#pragma unroll
        for (int f = 0; f < 8; f++) {
            o[f][0] *= sc0; o[f][1] *= sc0;
            o[f][2] *= sc1; o[f][3] *= sc1;
        }

        // ---- P = exp2(S - m), split+pack into A-fragments ----
        uint32_t ph[4][4], pl[4][4];
#pragma unroll
        for (int kf = 0; kf < 4; kf++) {
#pragma unroll
            for (int j = 0; j < 2; j++) {
                float* sf = s[2 * kf + j];
                float p0 = ex2f(sf[0] - mn0);
                float p1 = ex2f(sf[1] - mn0);
                float p2 = ex2f(sf[2] - mn1);
                float p3 = ex2f(sf[3] - mn1);
                lsum[0] += p0 + p1;
                lsum[1] += p2 + p3;
                split_pack(p0, p1, ph[kf][2 * j + 0], pl[kf][2 * j + 0]);
                split_pack(p2, p3, ph[kf][2 * j + 1], pl[kf][2 * j + 1]);
            }
        }

        // ---- O += P V (3-term split), V via ldmatrix.trans ----
#pragma unroll
        for (int kf = 0; kf < 4; kf++) {
#pragma unroll
            for (int nc = 0; nc < 4; nc++) {
                uint32_t bhh[4], bll[4];
                ldm_x4_t(bhh, sV + voff + kf * 16 * (LDA * 2) + nc * 32);
                ldm_x4_t(bll, sV + voff + kf * 16 * (LDA * 2) + 128 + nc * 32);
                mma16816(o[2 * nc],     ph[kf], bhh + 0);
                mma16816(o[2 * nc + 1], ph[kf], bhh + 2);
                mma16816(o[2 * nc],     pl[kf], bhh + 0);
                mma16816(o[2 * nc + 1], pl[kf], bhh + 2);
                mma16816(o[2 * nc],     ph[kf], bll + 0);
                mma16816(o[2 * nc + 1], ph[kf], bll + 2);
            }
        }
        __syncthreads();
    }

    // ---- finalize & store ctx [B,S,D] ----
    lsum[0] += __shfl_xor_sync(0xffffffffu, lsum[0], 1);
    lsum[0] += __shfl_xor_sync(0xffffffffu, lsum[0], 2);
    lsum[1] += __shfl_xor_sync(0xffffffffu, lsum[1], 1);
    lsum[1] += __shfl_xor_sync(0xffffffffu, lsum[1], 2);
    const float inv0 = 1.0f / lsum[0];
    const float inv1 = 1.0f / lsum[1];

    const int b = bh >> 4;
    const int h = bh & (HH - 1);
    const int r0 = q0 + w * 16 + (lane >> 2);
    const int col = h * HDD + 2 * (lane & 3);
    float* O0 = g_ctx + ((size_t)b * SS + r0) * DD + col;
    float* O1 = g_ctx + ((size_t)b * SS + r0 + 8) * DD + col;
#pragma unroll
    for (int f = 0; f < 8; f++) {
        float2 v0; v0.x = o[f][0] * inv0; v0.y = o[f][1] * inv0;
        float2 v1; v1.x = o[f][2] * inv1; v1.y = o[f][3] * inv1;
        *reinterpret_cast<float2*>(O0 + f * 8) = v0;
        *reinterpret_cast<float2*>(O1 + f * 8) = v1;
    }
}

// ---------------------------------------------------------------------------
// Launch
// ---------------------------------------------------------------------------
extern "C" void kernel_launch(void* const* d_in, const int* in_sizes, int n_in,
                              void* d_out, int out_size) {
    const float* query = (const float*)d_in[0];
    const float* key_i = (const float*)d_in[1];
    const float* value = (const float*)d_in[2];
    const float* Wq = (const float*)d_in[3];
    const float* Wk = (const float*)d_in[4];
    const float* Wv = (const float*)d_in[5];
    const float* Wo = (const float*)d_in[6];
    const float* bo = (const float*)d_in[7];
    float* out = (float*)d_out;

    __nv_bfloat16 *qs, *ks, *vs, *a2, *b2;
    float* ctxg;
    cudaGetSymbolAddress((void**)&qs, g_Qs);
    cudaGetSymbolAddress((void**)&ks, g_Ks);
    cudaGetSymbolAddress((void**)&vs, g_Vs);
    cudaGetSymbolAddress((void**)&ctxg, g_ctx);
    cudaGetSymbolAddress((void**)&a2, g_A2);
    cudaGetSymbolAddress((void**)&b2, g_B2);

    dim3 ggrid(DD / 128, MROWS / 128);      // (8, 32)
    const int CONV_A_BLOCKS = (MROWS * DD / 2 + 255) / 256;
    const int CONV_W_BLOCKS = (DD * DD / 2 + 255) / 256;

    // Q = query @ Wq^T  -> split bf16, scaled by log2(e)/32
    conv_split<0><<<CONV_A_BLOCKS, 256>>>(query, a2, MROWS);
    conv_split<1><<<CONV_W_BLOCKS, 256>>>(Wq, b2, DD);
    gemm_mma<2><<<ggrid, 256>>>(a2, b2, nullptr, qs);

    // K
    conv_split<0><<<CONV_A_BLOCKS, 256>>>(key_i, a2, MROWS);
    conv_split<1><<<CONV_W_BLOCKS, 256>>>(Wk, b2, DD);
    gemm_mma<3><<<ggrid, 256>>>(a2, b2, nullptr, ks);

    // V
    conv_split<0><<<CONV_A_BLOCKS, 256>>>(value, a2, MROWS);
    conv_split<1><<<CONV_W_BLOCKS, 256>>>(Wv, b2, DD);
    gemm_mma<3><<<ggrid, 256>>>(a2, b2, nullptr, vs);

    // Attention -> ctx [B,S,D]
    dim3 agrid(SS / 128, BB * HH);
    attn_mma<<<agrid, 256>>>();

    // Output projection with bias
    conv_split<0><<<CONV_A_BLOCKS, 256>>>(ctxg, a2, MROWS);
    conv_split<1><<<CONV_W_BLOCKS, 256>>>(Wo, b2, DD);
    gemm_mma<0><<<ggrid, 256>>>(a2, b2, bo, out);
}

// round 5
// speedup vs baseline: 4.5657x; 1.6047x over previous
#include <cuda_runtime.h>
#include <cuda_fp16.h>
#include <cstdint>

// Problem constants
#define BB 2
#define SS 2048
#define DD 1024
#define HH 16
#define HDD 64
#define MROWS (BB * SS)          // 4096
#define KS (2 * DD)              // 2048 (fp16 2-term split for GEMMs)
static constexpr float QMULT = 1.4426950408889634f / 32.0f;  // log2(e)/sqrt(D)

// ---------------------------------------------------------------------------
// Device scratch
// ---------------------------------------------------------------------------
__device__ __half g_Qs[(size_t)BB * HH * SS * 128];  // [BH,S,hi64|lo64]
__device__ __half g_Ks[(size_t)BB * HH * SS * 64];   // [BH,S,64] hi only
__device__ __half g_Vs[(size_t)BB * HH * SS * 64];   // [BH,S,64] hi only
__device__ float g_ctx[MROWS * DD];                  // [B,S,D]
__device__ __half g_A2[(size_t)MROWS * KS];          // 16 MB split activations
__device__ __half g_B2[(size_t)DD * KS];             //  4 MB split weights

// ---------------------------------------------------------------------------
// Helpers (baseline PTX only: cp.async / ldmatrix / mma.sync)
// ---------------------------------------------------------------------------
__device__ __forceinline__ uint32_t smem_u32(const void* p) {
    uint32_t a;
    asm("{ .reg .u64 t; cvta.to.shared.u64 t, %1; cvt.u32.u64 %0, t; }" : "=r"(a) : "l"(p));
    return a;
}
__device__ __forceinline__ void cp16(uint32_t s, const void* g) {
    asm volatile("cp.async.cg.shared.global [%0], [%1], 16;" :: "r"(s), "l"(g));
}
__device__ __forceinline__ void cp_commit() {
    asm volatile("cp.async.commit_group;" ::: "memory");
}
template <int N>
__device__ __forceinline__ void cp_wait() {
    asm volatile("cp.async.wait_group %0;" :: "n"(N) : "memory");
}
__device__ __forceinline__ void ldm_x4(uint32_t* r, uint32_t addr) {
    asm volatile("ldmatrix.sync.aligned.m8n8.x4.shared.b16 {%0,%1,%2,%3}, [%4];"
                 : "=r"(r[0]), "=r"(r[1]), "=r"(r[2]), "=r"(r[3]) : "r"(addr));
}
__device__ __forceinline__ void ldm_x4_t(uint32_t* r, uint32_t addr) {
    asm volatile("ldmatrix.sync.aligned.m8n8.x4.trans.shared.b16 {%0,%1,%2,%3}, [%4];"
                 : "=r"(r[0]), "=r"(r[1]), "=r"(r[2]), "=r"(r[3]) : "r"(addr));
}
__device__ __forceinline__ void mma16816(float* d, const uint32_t* a, const uint32_t* b) {
    asm volatile(
        "mma.sync.aligned.m16n8k16.row.col.f32.f16.f16.f32 "
        "{%0,%1,%2,%3}, {%4,%5,%6,%7}, {%8,%9}, {%0,%1,%2,%3};"
        : "+f"(d[0]), "+f"(d[1]), "+f"(d[2]), "+f"(d[3])
        : "r"(a[0]), "r"(a[1]), "r"(a[2]), "r"(a[3]), "r"(b[0]), "r"(b[1]));
}
__device__ __forceinline__ float ex2f(float x) {
    float r;
    asm("ex2.approx.ftz.f32 %0, %1;" : "=f"(r) : "f"(x));
    return r;
}
__device__ __forceinline__ void split_pack(float x, float y, uint32_t& hi, uint32_t& lo) {
    __half hx = __float2half_rn(x);
    __half hy = __float2half_rn(y);
    __half lx = __float2half_rn(x - __half2float(hx));
    __half ly = __float2half_rn(y - __half2float(hy));
    __half2 h2; h2.x = hx; h2.y = hy;
    __half2 l2; l2.x = lx; l2.y = ly;
    hi = *reinterpret_cast<uint32_t*>(&h2);
    lo = *reinterpret_cast<uint32_t*>(&l2);
}
__device__ __forceinline__ uint32_t pack_h2(float x, float y) {
    __half2 h2; h2.x = __float2half_rn(x); h2.y = __float2half_rn(y);
    return *reinterpret_cast<uint32_t*>(&h2);
}

// ---------------------------------------------------------------------------
// fp32 -> fp16 split with K-packing (for dense GEMMs).
// A-side (BSIDE=0): [hi | lo]; B-side (BSIDE=1): [hi | hi]
// dropped term: hi_A*lo_B ~ 2^-12 random -> ~1.4e-4 per GEMM.
// ---------------------------------------------------------------------------
template <int BSIDE>
__global__ __launch_bounds__(256) void conv_split(const float* __restrict__ in,
                                                  __half* __restrict__ out,
                                                  int rows) {
    int idx = blockIdx.x * 256 + threadIdx.x;
    int total = rows * (DD / 2);
    if (idx >= total) return;
    int r = idx / (DD / 2);
    int c2 = idx - r * (DD / 2);
    float2 x = reinterpret_cast<const float2*>(in)[(size_t)r * (DD / 2) + c2];
    __half h0 = __float2half_rn(x.x);
    __half h1 = __float2half_rn(x.y);
    __half2 hi; hi.x = h0; hi.y = h1;
    __half2* o = reinterpret_cast<__half2*>(out) + (size_t)r * (KS / 2) + c2;
    o[0] = hi;
    if (BSIDE) {
        o[DD / 2] = hi;
    } else {
        __half2 lo;
        lo.x = __float2half_rn(x.x - __half2float(h0));
        lo.y = __float2half_rn(x.y - __half2float(h1));
        o[DD / 2] = lo;
    }
}

// ---------------------------------------------------------------------------
// fp16 tensor-core GEMM: C[m,n] = sum_k A2[m,k]*B2[n,k]  (K = 2048 split)
// MODE 0: float out[m*DD+n] = C + bias[n]
// MODE 2: Q: fp16 out[((b*H+h)*S+s)*128 + hd] = hi(C*QMULT), +64 = lo
// MODE 3: K/V: fp16 out[((b*H+h)*S+s)*64 + hd] = hi(C)
// ---------------------------------------------------------------------------
#define LDHW 40   // smem row stride in halfwords (80 bytes)

template <int MODE>
__global__ __launch_bounds__(256) void gemm_mma(const __half* __restrict__ A2,
                                                const __half* __restrict__ B2,
                                                const float* __restrict__ bias,
                                                void* __restrict__ outv) {
    constexpr int NK = KS / 32;   // 64
    __shared__ __align__(16) __half sA[2][128 * LDHW];
    __shared__ __align__(16) __half sB[2][128 * LDHW];

    const int t = threadIdx.x;
    const int lane = t & 31;
    const int wid = t >> 5;
    const int wm = (wid >> 2) * 64;
    const int wn = (wid & 3) * 32;
    const int bm = blockIdx.y * 128;
    const int bn = blockIdx.x * 128;

    const uint32_t sAb[2] = { smem_u32(&sA[0][0]), smem_u32(&sA[1][0]) };
    const uint32_t sBb[2] = { smem_u32(&sB[0][0]), smem_u32(&sB[1][0]) };

    const int grow = t >> 1;
    const int gseg = t & 1;
    const __half* Ag = A2 + (size_t)(bm + grow) * KS + gseg * 16;
    const __half* Bg = B2 + (size_t)(bn + grow) * KS + gseg * 16;
    const uint32_t soff = (uint32_t)grow * (LDHW * 2) + gseg * 32;

    auto load_tile = [&](int buf, int kt) {
        const int k0 = kt * 32;
        cp16(sAb[buf] + soff,      Ag + k0);
        cp16(sAb[buf] + soff + 16, Ag + k0 + 8);
        cp16(sBb[buf] + soff,      Bg + k0);
        cp16(sBb[buf] + soff + 16, Bg + k0 + 8);
        cp_commit();
    };

    const uint32_t aoff = (uint32_t)(wm + (lane & 15)) * (LDHW * 2) + ((lane >> 4) << 4);
    const uint32_t boff = (uint32_t)(wn + (lane & 7) + ((lane >> 4) << 3)) * (LDHW * 2)
                        + (((lane >> 3) & 1) << 4);

    float d[4][4][4];
#pragma unroll
    for (int i = 0; i < 4; i++)
#pragma unroll
        for (int j = 0; j < 4; j++)
#pragma unroll
            for (int r = 0; r < 4; r++) d[i][j][r] = 0.0f;

    load_tile(0, 0);
    int cur = 0;
    for (int kt = 0; kt < NK; ++kt) {
        if (kt + 1 < NK) load_tile(cur ^ 1, kt + 1);
        if (kt + 1 < NK) cp_wait<1>(); else cp_wait<0>();
        __syncthreads();

        uint32_t a[4][2][4];
        uint32_t b[4][2][2];
#pragma unroll
        for (int mf = 0; mf < 4; mf++)
#pragma unroll
            for (int kf = 0; kf < 2; kf++)
                ldm_x4(a[mf][kf], sAb[cur] + aoff + mf * 16 * (LDHW * 2) + kf * 32);
#pragma unroll
        for (int nf2 = 0; nf2 < 2; nf2++)
#pragma unroll
            for (int kf = 0; kf < 2; kf++) {
                uint32_t r[4];
                ldm_x4(r, sBb[cur] + boff + nf2 * 16 * (LDHW * 2) + kf * 32);
                b[nf2 * 2 + 0][kf][0] = r[0]; b[nf2 * 2 + 0][kf][1] = r[1];
                b[nf2 * 2 + 1][kf][0] = r[2]; b[nf2 * 2 + 1][kf][1] = r[3];
            }
#pragma unroll
        for (int mf = 0; mf < 4; mf++)
#pragma unroll
            for (int nf = 0; nf < 4; nf++) {
                mma16816(d[mf][nf], a[mf][0], b[nf][0]);
                mma16816(d[mf][nf], a[mf][1], b[nf][1]);
            }
        __syncthreads();
        cur ^= 1;
    }

    const int mrow = bm + wm + (lane >> 2);
    const int ncol0 = bn + wn + (lane & 3) * 2;
#pragma unroll
    for (int mf = 0; mf < 4; mf++) {
#pragma unroll
        for (int half = 0; half < 2; half++) {
            const int m = mrow + mf * 16 + half * 8;
            if (MODE == 0) {
                float* out = (float*)outv;
                float* orow = out + (size_t)m * DD;
#pragma unroll
                for (int nf = 0; nf < 4; nf++) {
                    const int n = ncol0 + nf * 8;
                    float2 o;
                    o.x = d[mf][nf][half * 2 + 0] + bias[n];
                    o.y = d[mf][nf][half * 2 + 1] + bias[n + 1];
                    *reinterpret_cast<float2*>(orow + n) = o;
                }
            } else if (MODE == 2) {
                __half* out = (__half*)outv;
                const int b = m >> 11;
                const int s = m & (SS - 1);
#pragma unroll
                for (int nf = 0; nf < 4; nf++) {
                    const int n = ncol0 + nf * 8;
                    const int h = n >> 6;
                    const int hd = n & (HDD - 1);
                    __half* base = out + (((size_t)b * HH + h) * SS + s) * 128 + hd;
                    uint32_t hi, lo;
                    split_pack(d[mf][nf][half * 2 + 0] * QMULT,
                               d[mf][nf][half * 2 + 1] * QMULT, hi, lo);
                    *reinterpret_cast<uint32_t*>(base) = hi;
                    *reinterpret_cast<uint32_t*>(base + 64) = lo;
                }
            } else {
                __half* out = (__half*)outv;
                const int b = m >> 11;
                const int s = m & (SS - 1);
#pragma unroll
                for (int nf = 0; nf < 4; nf++) {
                    const int n = ncol0 + nf * 8;
                    const int h = n >> 6;
                    const int hd = n & (HDD - 1);
                    __half* base = out + (((size_t)b * HH + h) * SS + s) * 64 + hd;
                    *reinterpret_cast<uint32_t*>(base) =
                        pack_h2(d[mf][nf][half * 2 + 0], d[mf][nf][half * 2 + 1]);
                }
            }
        }
    }
}

// ---------------------------------------------------------------------------
// Tensor-core flash attention (fp16 2-term).
// grid (S/128, B*H), 256 threads (8 warps x 16 q rows).
// Q pre-split [S, hi64|lo64]; K,V single fp16 [S,64]. 64-key tiles.
// S = q_hi*k + q_lo*k ; O += p_hi*v + p_lo*v ; online softmax in registers.
// ---------------------------------------------------------------------------
#define LDA 136   // Q smem row stride in halfwords (272B)
#define LDK 72    // K/V smem row stride in halfwords (144B)

__global__ __launch_bounds__(256) void attn_mma() {
    __shared__ __align__(16) __half smem[128 * LDA];  // 34,816 B (Q stage, then K|V)

    const int t = threadIdx.x;
    const int lane = t & 31;
    const int w = t >> 5;
    const int bh = blockIdx.y;
    const int q0 = blockIdx.x * 128;

    const uint32_t sbase = smem_u32(smem);
    const uint32_t sK = sbase;
    const uint32_t sV = sbase + 64 * (LDK * 2);

    // ---- stage Q tile (128 rows x 256B), load A-fragments, free the smem ----
    const __half* Qg = g_Qs + ((size_t)bh * SS + q0) * 128;
#pragma unroll
    for (int i = 0; i < 8; i++) {
        int idx = i * 256 + t;
        int row = idx >> 4, ch = idx & 15;
        cp16(sbase + row * (LDA * 2) + ch * 16, Qg + (size_t)row * 128 + ch * 8);
    }
    cp_commit(); cp_wait<0>();
    __syncthreads();

    uint32_t qa[2][4][4];   // [hi/lo][kf][reg]
    const uint32_t aoff = (uint32_t)(w * 16 + (lane & 15)) * (LDA * 2) + ((lane >> 4) << 4);
#pragma unroll
    for (int kf = 0; kf < 4; kf++) {
        ldm_x4(qa[0][kf], sbase + aoff + kf * 32);
        ldm_x4(qa[1][kf], sbase + aoff + 128 + kf * 32);
    }
    __syncthreads();

    // ---- state ----
    float o[8][4];
#pragma unroll
    for (int f = 0; f < 8; f++)
#pragma unroll
        for (int r = 0; r < 4; r++) o[f][r] = 0.0f;
    float mrow[2] = { -1e30f, -1e30f };
    float lsum[2] = { 0.0f, 0.0f };

    const __half* Kg = g_Ks + (size_t)bh * SS * 64;
    const __half* Vg = g_Vs + (size_t)bh * SS * 64;

    const uint32_t boff = (uint32_t)((lane & 7) + ((lane >> 4) << 3)) * (LDK * 2)
                        + (((lane >> 3) & 1) << 4);
    const uint32_t voff = (uint32_t)(lane & 15) * (LDK * 2) + ((lane >> 4) << 4);

    for (int k0 = 0; k0 < SS; k0 += 64) {
        // load K,V tiles: 64 rows x 128B each
#pragma unroll
        for (int i = 0; i < 2; i++) {
            int idx = i * 256 + t;
            int row = idx >> 3, ch = idx & 7;
            cp16(sK + row * (LDK * 2) + ch * 16, Kg + ((size_t)(k0 + row)) * 64 + ch * 8);
            cp16(sV + row * (LDK * 2) + ch * 16, Vg + ((size_t)(k0 + row)) * 64 + ch * 8);
        }
        cp_commit(); cp_wait<0>();
        __syncthreads();

        // ---- S = Q K^T (2-term), in log2 domain ----
        float s[8][4];
#pragma unroll
        for (int f = 0; f < 8; f++)
#pragma unroll
            for (int r = 0; r < 4; r++) s[f][r] = 0.0f;
#pragma unroll
        for (int kf = 0; kf < 4; kf++) {
#pragma unroll
            for (int nc = 0; nc < 4; nc++) {
                uint32_t bk[4];
                ldm_x4(bk, sK + boff + nc * 16 * (LDK * 2) + kf * 32);
                mma16816(s[2 * nc],     qa[0][kf], bk + 0);
                mma16816(s[2 * nc + 1], qa[0][kf], bk + 2);
                mma16816(s[2 * nc],     qa[1][kf], bk + 0);
                mma16816(s[2 * nc + 1], qa[1][kf], bk + 2);
            }
        }

        // ---- online softmax ----
        float tm0 = -1e30f, tm1 = -1e30f;
#pragma unroll
        for (int f = 0; f < 8; f++) {
            tm0 = fmaxf(tm0, fmaxf(s[f][0], s[f][1]));
            tm1 = fmaxf(tm1, fmaxf(s[f][2], s[f][3]));
        }
        tm0 = fmaxf(tm0, __shfl_xor_sync(0xffffffffu, tm0, 1));
        tm0 = fmaxf(tm0, __shfl_xor_sync(0xffffffffu, tm0, 2));
        tm1 = fmaxf(tm1, __shfl_xor_sync(0xffffffffu, tm1, 1));
        tm1 = fmaxf(tm1, __shfl_xor_sync(0xffffffffu, tm1, 2));
        const float mn0 = fmaxf(mrow[0], tm0);
        const float mn1 = fmaxf(mrow[1], tm1);
        const float sc0 = ex2f(mrow[0] - mn0);
        const float sc1 = ex2f(mrow[1] - mn1);
        mrow[0] = mn0; mrow[1] = mn1;
        lsum[0] *= sc0; lsum[1] *= sc1;
#pragma unroll
        for (int f = 0; f < 8; f++) {
            o[f][0] *= sc0; o[f][1] *= sc0;
            o[f][2] *= sc1; o[f][3] *= sc1;
        }

        // ---- P = exp2(S - m), split+pack into A-fragments ----
        uint32_t ph[4][4], pl[4][4];
#pragma unroll
        for (int kf = 0; kf < 4; kf++) {
#pragma unroll
            for (int j = 0; j < 2; j++) {
                float* sf = s[2 * kf + j];
                float p0 = ex2f(sf[0] - mn0);
                float p1 = ex2f(sf[1] - mn0);
                float p2 = ex2f(sf[2] - mn1);
                float p3 = ex2f(sf[3] - mn1);
                lsum[0] += p0 + p1;
                lsum[1] += p2 + p3;
                split_pack(p0, p1, ph[kf][2 * j + 0], pl[kf][2 * j + 0]);
                split_pack(p2, p3, ph[kf][2 * j + 1], pl[kf][2 * j + 1]);
            }
        }

        // ---- O += P V (2-term), V via ldmatrix.trans ----
#pragma unroll
        for (int kf = 0; kf < 4; kf++) {
#pragma unroll
            for (int nc = 0; nc < 4; nc++) {
                uint32_t bv[4];
                ldm_x4_t(bv, sV + voff + kf * 16 * (LDK * 2) + nc * 32);
                mma16816(o[2 * nc],     ph[kf], bv + 0);
                mma16816(o[2 * nc + 1], ph[kf], bv + 2);
                mma16816(o[2 * nc],     pl[kf], bv + 0);
                mma16816(o[2 * nc + 1], pl[kf], bv + 2);
            }
        }
        __syncthreads();
    }

    // ---- finalize & store ctx [B,S,D] ----
    lsum[0] += __shfl_xor_sync(0xffffffffu, lsum[0], 1);
    lsum[0] += __shfl_xor_sync(0xffffffffu, lsum[0], 2);
    lsum[1] += __shfl_xor_sync(0xffffffffu, lsum[1], 1);
    lsum[1] += __shfl_xor_sync(0xffffffffu, lsum[1], 2);
    const float inv0 = 1.0f / lsum[0];
    const float inv1 = 1.0f / lsum[1];

    const int b = bh >> 4;
    const int h = bh & (HH - 1);
    const int r0 = q0 + w * 16 + (lane >> 2);
    const int col = h * HDD + 2 * (lane & 3);
    float* O0 = g_ctx + ((size_t)b * SS + r0) * DD + col;
    float* O1 = g_ctx + ((size_t)b * SS + r0 + 8) * DD + col;
#pragma unroll
    for (int f = 0; f < 8; f++) {
        float2 v0; v0.x = o[f][0] * inv0; v0.y = o[f][1] * inv0;
        float2 v1; v1.x = o[f][2] * inv1; v1.y = o[f][3] * inv1;
        *reinterpret_cast<float2*>(O0 + f * 8) = v0;
        *reinterpret_cast<float2*>(O1 + f * 8) = v1;
    }
}

// ---------------------------------------------------------------------------
// Launch
// ---------------------------------------------------------------------------
extern "C" void kernel_launch(void* const* d_in, const int* in_sizes, int n_in,
                              void* d_out, int out_size) {
    const float* query = (const float*)d_in[0];
    const float* key_i = (const float*)d_in[1];
    const float* value = (const float*)d_in[2];
    const float* Wq = (const float*)d_in[3];
    const float* Wk = (const float*)d_in[4];
    const float* Wv = (const float*)d_in[5];
    const float* Wo = (const float*)d_in[6];
    const float* bo = (const float*)d_in[7];
    float* out = (float*)d_out;

    __half *qs, *ks, *vs, *a2, *b2;
    float* ctxg;
    cudaGetSymbolAddress((void**)&qs, g_Qs);
    cudaGetSymbolAddress((void**)&ks, g_Ks);
    cudaGetSymbolAddress((void**)&vs, g_Vs);
    cudaGetSymbolAddress((void**)&ctxg, g_ctx);
    cudaGetSymbolAddress((void**)&a2, g_A2);
    cudaGetSymbolAddress((void**)&b2, g_B2);

    dim3 ggrid(DD / 128, MROWS / 128);      // (8, 32)
    const int CONV_A_BLOCKS = (MROWS * DD / 2 + 255) / 256;
    const int CONV_W_BLOCKS = (DD * DD / 2 + 255) / 256;

    // Q = query @ Wq^T  -> split fp16, scaled by log2(e)/32
    conv_split<0><<<CONV_A_BLOCKS, 256>>>(query, a2, MROWS);
    conv_split<1><<<CONV_W_BLOCKS, 256>>>(Wq, b2, DD);
    gemm_mma<2><<<ggrid, 256>>>(a2, b2, nullptr, qs);

    // K -> single fp16
    conv_split<0><<<CONV_A_BLOCKS, 256>>>(key_i, a2, MROWS);
    conv_split<1><<<CONV_W_BLOCKS, 256>>>(Wk, b2, DD);
    gemm_mma<3><<<ggrid, 256>>>(a2, b2, nullptr, ks);

    // V -> single fp16
    conv_split<0><<<CONV_A_BLOCKS, 256>>>(value, a2, MROWS);
    conv_split<1><<<CONV_W_BLOCKS, 256>>>(Wv, b2, DD);
    gemm_mma<3><<<ggrid, 256>>>(a2, b2, nullptr, vs);

    // Attention -> ctx [B,S,D]
    dim3 agrid(SS / 128, BB * HH);
    attn_mma<<<agrid, 256>>>();

    // Output projection with bias
    conv_split<0><<<CONV_A_BLOCKS, 256>>>(ctxg, a2, MROWS);
    conv_split<1><<<CONV_W_BLOCKS, 256>>>(Wo, b2, DD);
    gemm_mma<0><<<ggrid, 256>>>(a2, b2, bo, out);
}

// round 6
// speedup vs baseline: 8.0342x; 1.7597x over previous
#include <cuda_runtime.h>
#include <cuda_fp16.h>
#include <cstdint>

// Problem constants
#define BB 2
#define SS 2048
#define DD 1024
#define HH 16
#define HDD 64
#define MROWS (BB * SS)          // 4096
static constexpr float QMULT = 1.4426950408889634f / 32.0f;  // log2(e)/sqrt(D)

// ---------------------------------------------------------------------------
// Device scratch
// ---------------------------------------------------------------------------
__device__ __half g_Qs[(size_t)BB * HH * SS * 64];   // [BH,S,64] (pre-scaled)
__device__ __half g_Ks[(size_t)BB * HH * SS * 64];   // [BH,S,64]
__device__ __half g_Vs[(size_t)BB * HH * SS * 64];   // [BH,S,64]
__device__ float g_ctx[MROWS * DD];                  // [B,S,D]
__device__ __half g_A2[(size_t)MROWS * DD];          // 8 MB fp16 activations
__device__ __half g_B2[(size_t)DD * DD];             // 2 MB fp16 weights

// ---------------------------------------------------------------------------
// Helpers (baseline PTX only: cp.async / ldmatrix / mma.sync)
// ---------------------------------------------------------------------------
__device__ __forceinline__ uint32_t smem_u32(const void* p) {
    uint32_t a;
    asm("{ .reg .u64 t; cvta.to.shared.u64 t, %1; cvt.u32.u64 %0, t; }" : "=r"(a) : "l"(p));
    return a;
}
__device__ __forceinline__ void cp16(uint32_t s, const void* g) {
    asm volatile("cp.async.cg.shared.global [%0], [%1], 16;" :: "r"(s), "l"(g));
}
__device__ __forceinline__ void cp_commit() {
    asm volatile("cp.async.commit_group;" ::: "memory");
}
template <int N>
__device__ __forceinline__ void cp_wait() {
    asm volatile("cp.async.wait_group %0;" :: "n"(N) : "memory");
}
__device__ __forceinline__ void ldm_x4(uint32_t* r, uint32_t addr) {
    asm volatile("ldmatrix.sync.aligned.m8n8.x4.shared.b16 {%0,%1,%2,%3}, [%4];"
                 : "=r"(r[0]), "=r"(r[1]), "=r"(r[2]), "=r"(r[3]) : "r"(addr));
}
__device__ __forceinline__ void ldm_x4_t(uint32_t* r, uint32_t addr) {
    asm volatile("ldmatrix.sync.aligned.m8n8.x4.trans.shared.b16 {%0,%1,%2,%3}, [%4];"
                 : "=r"(r[0]), "=r"(r[1]), "=r"(r[2]), "=r"(r[3]) : "r"(addr));
}
__device__ __forceinline__ void mma16816(float* d, const uint32_t* a, const uint32_t* b) {
    asm volatile(
        "mma.sync.aligned.m16n8k16.row.col.f32.f16.f16.f32 "
        "{%0,%1,%2,%3}, {%4,%5,%6,%7}, {%8,%9}, {%0,%1,%2,%3};"
        : "+f"(d[0]), "+f"(d[1]), "+f"(d[2]), "+f"(d[3])
        : "r"(a[0]), "r"(a[1]), "r"(a[2]), "r"(a[3]), "r"(b[0]), "r"(b[1]));
}
__device__ __forceinline__ float ex2f(float x) {
    float r;
    asm("ex2.approx.ftz.f32 %0, %1;" : "=f"(r) : "f"(x));
    return r;
}
__device__ __forceinline__ uint32_t pack_h2(float x, float y) {
    __half2 h2; h2.x = __float2half_rn(x); h2.y = __float2half_rn(y);
    return *reinterpret_cast<uint32_t*>(&h2);
}

// ---------------------------------------------------------------------------
// fp32 -> fp16 convert: [rows,1024] -> [rows,1024]
// ---------------------------------------------------------------------------
__global__ __launch_bounds__(256) void conv_half(const float* __restrict__ in,
                                                 __half* __restrict__ out,
                                                 int rows) {
    int idx = blockIdx.x * 256 + threadIdx.x;   // float4 index
    int total = rows * (DD / 4);
    if (idx >= total) return;
    float4 x = reinterpret_cast<const float4*>(in)[idx];
    __half2 a; a.x = __float2half_rn(x.x); a.y = __float2half_rn(x.y);
    __half2 b; b.x = __float2half_rn(x.z); b.y = __float2half_rn(x.w);
    __half2* o = reinterpret_cast<__half2*>(out) + idx * 2;
    o[0] = a; o[1] = b;
}

// ---------------------------------------------------------------------------
// fp16 tensor-core GEMM: C[m,n] = sum_k A2[m,k]*B2[n,k]  (K = 1024)
// MODE 0: float out[m*DD+n] = C + bias[n]
// MODE 2: Q: fp16 out[((b*H+h)*S+s)*64 + hd] = C*QMULT
// MODE 3: K/V: fp16 out[((b*H+h)*S+s)*64 + hd] = C
// ---------------------------------------------------------------------------
#define LDHW 40   // smem row stride in halfwords (80 bytes)

template <int MODE>
__global__ __launch_bounds__(256) void gemm_mma(const __half* __restrict__ A2,
                                                const __half* __restrict__ B2,
                                                const float* __restrict__ bias,
                                                void* __restrict__ outv) {
    constexpr int NK = DD / 32;   // 32
    __shared__ __align__(16) __half sA[2][128 * LDHW];
    __shared__ __align__(16) __half sB[2][128 * LDHW];

    const int t = threadIdx.x;
    const int lane = t & 31;
    const int wid = t >> 5;
    const int wm = (wid >> 2) * 64;
    const int wn = (wid & 3) * 32;
    const int bm = blockIdx.y * 128;
    const int bn = blockIdx.x * 128;

    const uint32_t sAb[2] = { smem_u32(&sA[0][0]), smem_u32(&sA[1][0]) };
    const uint32_t sBb[2] = { smem_u32(&sB[0][0]), smem_u32(&sB[1][0]) };

    const int grow = t >> 1;
    const int gseg = t & 1;
    const __half* Ag = A2 + (size_t)(bm + grow) * DD + gseg * 16;
    const __half* Bg = B2 + (size_t)(bn + grow) * DD + gseg * 16;
    const uint32_t soff = (uint32_t)grow * (LDHW * 2) + gseg * 32;

    auto load_tile = [&](int buf, int kt) {
        const int k0 = kt * 32;
        cp16(sAb[buf] + soff,      Ag + k0);
        cp16(sAb[buf] + soff + 16, Ag + k0 + 8);
        cp16(sBb[buf] + soff,      Bg + k0);
        cp16(sBb[buf] + soff + 16, Bg + k0 + 8);
        cp_commit();
    };

    const uint32_t aoff = (uint32_t)(wm + (lane & 15)) * (LDHW * 2) + ((lane >> 4) << 4);
    const uint32_t boff = (uint32_t)(wn + (lane & 7) + ((lane >> 4) << 3)) * (LDHW * 2)
                        + (((lane >> 3) & 1) << 4);

    float d[4][4][4];
#pragma unroll
    for (int i = 0; i < 4; i++)
#pragma unroll
        for (int j = 0; j < 4; j++)
#pragma unroll
            for (int r = 0; r < 4; r++) d[i][j][r] = 0.0f;

    load_tile(0, 0);
    int cur = 0;
    for (int kt = 0; kt < NK; ++kt) {
        if (kt + 1 < NK) load_tile(cur ^ 1, kt + 1);
        if (kt + 1 < NK) cp_wait<1>(); else cp_wait<0>();
        __syncthreads();

        uint32_t a[4][2][4];
        uint32_t b[4][2][2];
#pragma unroll
        for (int mf = 0; mf < 4; mf++)
#pragma unroll
            for (int kf = 0; kf < 2; kf++)
                ldm_x4(a[mf][kf], sAb[cur] + aoff + mf * 16 * (LDHW * 2) + kf * 32);
#pragma unroll
        for (int nf2 = 0; nf2 < 2; nf2++)
#pragma unroll
            for (int kf = 0; kf < 2; kf++) {
                uint32_t r[4];
                ldm_x4(r, sBb[cur] + boff + nf2 * 16 * (LDHW * 2) + kf * 32);
                b[nf2 * 2 + 0][kf][0] = r[0]; b[nf2 * 2 + 0][kf][1] = r[1];
                b[nf2 * 2 + 1][kf][0] = r[2]; b[nf2 * 2 + 1][kf][1] = r[3];
            }
#pragma unroll
        for (int mf = 0; mf < 4; mf++)
#pragma unroll
            for (int nf = 0; nf < 4; nf++) {
                mma16816(d[mf][nf], a[mf][0], b[nf][0]);
                mma16816(d[mf][nf], a[mf][1], b[nf][1]);
            }
        __syncthreads();
        cur ^= 1;
    }

    const int mrow = bm + wm + (lane >> 2);
    const int ncol0 = bn + wn + (lane & 3) * 2;
#pragma unroll
    for (int mf = 0; mf < 4; mf++) {
#pragma unroll
        for (int half = 0; half < 2; half++) {
            const int m = mrow + mf * 16 + half * 8;
            if (MODE == 0) {
                float* out = (float*)outv;
                float* orow = out + (size_t)m * DD;
#pragma unroll
                for (int nf = 0; nf < 4; nf++) {
                    const int n = ncol0 + nf * 8;
                    float2 o;
                    o.x = d[mf][nf][half * 2 + 0] + bias[n];
                    o.y = d[mf][nf][half * 2 + 1] + bias[n + 1];
                    *reinterpret_cast<float2*>(orow + n) = o;
                }
            } else {
                __half* out = (__half*)outv;
                const float mult = (MODE == 2) ? QMULT : 1.0f;
                const int b = m >> 11;
                const int s = m & (SS - 1);
#pragma unroll
                for (int nf = 0; nf < 4; nf++) {
                    const int n = ncol0 + nf * 8;
                    const int h = n >> 6;
                    const int hd = n & (HDD - 1);
                    __half* base = out + (((size_t)b * HH + h) * SS + s) * 64 + hd;
                    *reinterpret_cast<uint32_t*>(base) =
                        pack_h2(d[mf][nf][half * 2 + 0] * mult,
                                d[mf][nf][half * 2 + 1] * mult);
                }
            }
        }
    }
}

// ---------------------------------------------------------------------------
// Tensor-core flash attention (plain fp16 operands, fp32 accum/softmax).
// grid (S/128, B*H), 256 threads (8 warps x 16 q rows).
// Q/K/V fp16 [S,64]. 64-key tiles; online softmax in registers.
// ---------------------------------------------------------------------------
#define LDK 72    // K/V/Q smem row stride in halfwords (144B)

__global__ __launch_bounds__(256) void attn_mma() {
    __shared__ __align__(16) __half smem[128 * LDK];  // 18,432 B

    const int t = threadIdx.x;
    const int lane = t & 31;
    const int w = t >> 5;
    const int bh = blockIdx.y;
    const int q0 = blockIdx.x * 128;

    const uint32_t sbase = smem_u32(smem);
    const uint32_t sK = sbase;
    const uint32_t sV = sbase + 64 * (LDK * 2);

    // ---- stage Q tile (128 rows x 128B), load A-fragments, free the smem ----
    const __half* Qg = g_Qs + ((size_t)bh * SS + q0) * 64;
#pragma unroll
    for (int i = 0; i < 4; i++) {
        int idx = i * 256 + t;
        int row = idx >> 3, ch = idx & 7;
        cp16(sbase + row * (LDK * 2) + ch * 16, Qg + (size_t)row * 64 + ch * 8);
    }
    cp_commit(); cp_wait<0>();
    __syncthreads();

    uint32_t qa[4][4];   // [kf][reg]
    const uint32_t aoff = (uint32_t)(w * 16 + (lane & 15)) * (LDK * 2) + ((lane >> 4) << 4);
#pragma unroll
    for (int kf = 0; kf < 4; kf++) ldm_x4(qa[kf], sbase + aoff + kf * 32);
    __syncthreads();

    // ---- state ----
    float o[8][4];
#pragma unroll
    for (int f = 0; f < 8; f++)
#pragma unroll
        for (int r = 0; r < 4; r++) o[f][r] = 0.0f;
    float mrow[2] = { -1e30f, -1e30f };
    float lsum[2] = { 0.0f, 0.0f };

    const __half* Kg = g_Ks + (size_t)bh * SS * 64;
    const __half* Vg = g_Vs + (size_t)bh * SS * 64;

    const uint32_t boff = (uint32_t)((lane & 7) + ((lane >> 4) << 3)) * (LDK * 2)
                        + (((lane >> 3) & 1) << 4);
    const uint32_t voff = (uint32_t)(lane & 15) * (LDK * 2) + ((lane >> 4) << 4);

    for (int k0 = 0; k0 < SS; k0 += 64) {
        // load K,V tiles: 64 rows x 128B each
#pragma unroll
        for (int i = 0; i < 2; i++) {
            int idx = i * 256 + t;
            int row = idx >> 3, ch = idx & 7;
            cp16(sK + row * (LDK * 2) + ch * 16, Kg + ((size_t)(k0 + row)) * 64 + ch * 8);
            cp16(sV + row * (LDK * 2) + ch * 16, Vg + ((size_t)(k0 + row)) * 64 + ch * 8);
        }
        cp_commit(); cp_wait<0>();
        __syncthreads();

        // ---- S = Q K^T (log2 domain, QMULT pre-folded) ----
        float s[8][4];
#pragma unroll
        for (int f = 0; f < 8; f++)
#pragma unroll
            for (int r = 0; r < 4; r++) s[f][r] = 0.0f;
#pragma unroll
        for (int kf = 0; kf < 4; kf++) {
#pragma unroll
            for (int nc = 0; nc < 4; nc++) {
                uint32_t bk[4];
                ldm_x4(bk, sK + boff + nc * 16 * (LDK * 2) + kf * 32);
                mma16816(s[2 * nc],     qa[kf], bk + 0);
                mma16816(s[2 * nc + 1], qa[kf], bk + 2);
            }
        }

        // ---- online softmax ----
        float tm0 = -1e30f, tm1 = -1e30f;
#pragma unroll
        for (int f = 0; f < 8; f++) {
            tm0 = fmaxf(tm0, fmaxf(s[f][0], s[f][1]));
            tm1 = fmaxf(tm1, fmaxf(s[f][2], s[f][3]));
        }
        tm0 = fmaxf(tm0, __shfl_xor_sync(0xffffffffu, tm0, 1));
        tm0 = fmaxf(tm0, __shfl_xor_sync(0xffffffffu, tm0, 2));
        tm1 = fmaxf(tm1, __shfl_xor_sync(0xffffffffu, tm1, 1));
        tm1 = fmaxf(tm1, __shfl_xor_sync(0xffffffffu, tm1, 2));
        const float mn0 = fmaxf(mrow[0], tm0);
        const float mn1 = fmaxf(mrow[1], tm1);
        const float sc0 = ex2f(mrow[0] - mn0);
        const float sc1 = ex2f(mrow[1] - mn1);
        mrow[0] = mn0; mrow[1] = mn1;
        lsum[0] *= sc0; lsum[1] *= sc1;
#pragma unroll
        for (int f = 0; f < 8; f++) {
            o[f][0] *= sc0; o[f][1] *= sc0;
            o[f][2] *= sc1; o[f][3] *= sc1;
        }

        // ---- P = exp2(S - m), pack into A-fragments ----
        uint32_t ph[4][4];
#pragma unroll
        for (int kf = 0; kf < 4; kf++) {
#pragma unroll
            for (int j = 0; j < 2; j++) {
                float* sf = s[2 * kf + j];
                float p0 = ex2f(sf[0] - mn0);
                float p1 = ex2f(sf[1] - mn0);
                float p2 = ex2f(sf[2] - mn1);
                float p3 = ex2f(sf[3] - mn1);
                lsum[0] += p0 + p1;
                lsum[1] += p2 + p3;
                ph[kf][2 * j + 0] = pack_h2(p0, p1);
                ph[kf][2 * j + 1] = pack_h2(p2, p3);
            }
        }

        // ---- O += P V, V via ldmatrix.trans ----
#pragma unroll
        for (int kf = 0; kf < 4; kf++) {
#pragma unroll
            for (int nc = 0; nc < 4; nc++) {
                uint32_t bv[4];
                ldm_x4_t(bv, sV + voff + kf * 16 * (LDK * 2) + nc * 32);
                mma16816(o[2 * nc],     ph[kf], bv + 0);
                mma16816(o[2 * nc + 1], ph[kf], bv + 2);
            }
        }
        __syncthreads();
    }

    // ---- finalize & store ctx [B,S,D] ----
    lsum[0] += __shfl_xor_sync(0xffffffffu, lsum[0], 1);
    lsum[0] += __shfl_xor_sync(0xffffffffu, lsum[0], 2);
    lsum[1] += __shfl_xor_sync(0xffffffffu, lsum[1], 1);
    lsum[1] += __shfl_xor_sync(0xffffffffu, lsum[1], 2);
    const float inv0 = 1.0f / lsum[0];
    const float inv1 = 1.0f / lsum[1];

    const int b = bh >> 4;
    const int h = bh & (HH - 1);
    const int r0 = q0 + w * 16 + (lane >> 2);
    const int col = h * HDD + 2 * (lane & 3);
    float* O0 = g_ctx + ((size_t)b * SS + r0) * DD + col;
    float* O1 = g_ctx + ((size_t)b * SS + r0 + 8) * DD + col;
#pragma unroll
    for (int f = 0; f < 8; f++) {
        float2 v0; v0.x = o[f][0] * inv0; v0.y = o[f][1] * inv0;
        float2 v1; v1.x = o[f][2] * inv1; v1.y = o[f][3] * inv1;
        *reinterpret_cast<float2*>(O0 + f * 8) = v0;
        *reinterpret_cast<float2*>(O1 + f * 8) = v1;
    }
}

// ---------------------------------------------------------------------------
// Launch
// ---------------------------------------------------------------------------
extern "C" void kernel_launch(void* const* d_in, const int* in_sizes, int n_in,
                              void* d_out, int out_size) {
    const float* query = (const float*)d_in[0];
    const float* key_i = (const float*)d_in[1];
    const float* value = (const float*)d_in[2];
    const float* Wq = (const float*)d_in[3];
    const float* Wk = (const float*)d_in[4];
    const float* Wv = (const float*)d_in[5];
    const float* Wo = (const float*)d_in[6];
    const float* bo = (const float*)d_in[7];
    float* out = (float*)d_out;

    __half *qs, *ks, *vs, *a2, *b2;
    float* ctxg;
    cudaGetSymbolAddress((void**)&qs, g_Qs);
    cudaGetSymbolAddress((void**)&ks, g_Ks);
    cudaGetSymbolAddress((void**)&vs, g_Vs);
    cudaGetSymbolAddress((void**)&ctxg, g_ctx);
    cudaGetSymbolAddress((void**)&a2, g_A2);
    cudaGetSymbolAddress((void**)&b2, g_B2);

    dim3 ggrid(DD / 128, MROWS / 128);      // (8, 32)
    const int CONV_A_BLOCKS = (MROWS * DD / 4 + 255) / 256;  // 4096
    const int CONV_W_BLOCKS = (DD * DD / 4 + 255) / 256;     // 1024

    // Q = query @ Wq^T  -> fp16, scaled by log2(e)/32
    conv_half<<<CONV_A_BLOCKS, 256>>>(query, a2, MROWS);
    conv_half<<<CONV_W_BLOCKS, 256>>>(Wq, b2, DD);
    gemm_mma<2><<<ggrid, 256>>>(a2, b2, nullptr, qs);

    // K
    conv_half<<<CONV_A_BLOCKS, 256>>>(key_i, a2, MROWS);
    conv_half<<<CONV_W_BLOCKS, 256>>>(Wk, b2, DD);
    gemm_mma<3><<<ggrid, 256>>>(a2, b2, nullptr, ks);

    // V
    conv_half<<<CONV_A_BLOCKS, 256>>>(value, a2, MROWS);
    conv_half<<<CONV_W_BLOCKS, 256>>>(Wv, b2, DD);
    gemm_mma<3><<<ggrid, 256>>>(a2, b2, nullptr, vs);

    // Attention -> ctx [B,S,D]
    dim3 agrid(SS / 128, BB * HH);
    attn_mma<<<agrid, 256>>>();

    // Output projection with bias
    conv_half<<<CONV_A_BLOCKS, 256>>>(ctxg, a2, MROWS);
    conv_half<<<CONV_W_BLOCKS, 256>>>(Wo, b2, DD);
    gemm_mma<0><<<ggrid, 256>>>(a2, b2, bo, out);
}

// round 7
// speedup vs baseline: 8.4994x; 1.0579x over previous
#include <cuda_runtime.h>
#include <cuda_fp16.h>
#include <cstdint>

// Problem constants
#define BB 2
#define SS 2048
#define DD 1024
#define HH 16
#define HDD 64
#define MROWS (BB * SS)          // 4096
static constexpr float QMULT = 1.4426950408889634f / 32.0f;  // log2(e)/sqrt(D)

// ---------------------------------------------------------------------------
// Device scratch
// ---------------------------------------------------------------------------
__device__ __half g_Qs[(size_t)BB * HH * SS * 64];   // [BH,S,64] (pre-scaled)
__device__ __half g_Ks[(size_t)BB * HH * SS * 64];
__device__ __half g_Vs[(size_t)BB * HH * SS * 64];
__device__ __half g_ctxh[(size_t)MROWS * DD];        // [B*S, D] fp16 ctx
__device__ __half g_W16[(size_t)4 * DD * DD];        // Wq|Wk|Wv|Wo fp16

// ---------------------------------------------------------------------------
// Helpers (baseline PTX only: cp.async / ldmatrix / mma.sync)
// ---------------------------------------------------------------------------
__device__ __forceinline__ uint32_t smem_u32(const void* p) {
    uint32_t a;
    asm("{ .reg .u64 t; cvta.to.shared.u64 t, %1; cvt.u32.u64 %0, t; }" : "=r"(a) : "l"(p));
    return a;
}
__device__ __forceinline__ void cp16(uint32_t s, const void* g) {
    asm volatile("cp.async.cg.shared.global [%0], [%1], 16;" :: "r"(s), "l"(g));
}
__device__ __forceinline__ void cp_commit() {
    asm volatile("cp.async.commit_group;" ::: "memory");
}
template <int N>
__device__ __forceinline__ void cp_wait() {
    asm volatile("cp.async.wait_group %0;" :: "n"(N) : "memory");
}
__device__ __forceinline__ void ldm_x4(uint32_t* r, uint32_t addr) {
    asm volatile("ldmatrix.sync.aligned.m8n8.x4.shared.b16 {%0,%1,%2,%3}, [%4];"
                 : "=r"(r[0]), "=r"(r[1]), "=r"(r[2]), "=r"(r[3]) : "r"(addr));
}
__device__ __forceinline__ void ldm_x4_t(uint32_t* r, uint32_t addr) {
    asm volatile("ldmatrix.sync.aligned.m8n8.x4.trans.shared.b16 {%0,%1,%2,%3}, [%4];"
                 : "=r"(r[0]), "=r"(r[1]), "=r"(r[2]), "=r"(r[3]) : "r"(addr));
}
__device__ __forceinline__ void mma16816(float* d, const uint32_t* a, const uint32_t* b) {
    asm volatile(
        "mma.sync.aligned.m16n8k16.row.col.f32.f16.f16.f32 "
        "{%0,%1,%2,%3}, {%4,%5,%6,%7}, {%8,%9}, {%0,%1,%2,%3};"
        : "+f"(d[0]), "+f"(d[1]), "+f"(d[2]), "+f"(d[3])
        : "r"(a[0]), "r"(a[1]), "r"(a[2]), "r"(a[3]), "r"(b[0]), "r"(b[1]));
}
__device__ __forceinline__ float ex2f(float x) {
    float r;
    asm("ex2.approx.ftz.f32 %0, %1;" : "=f"(r) : "f"(x));
    return r;
}
__device__ __forceinline__ uint32_t pack_h2(float x, float y) {
    __half2 h2; h2.x = __float2half_rn(x); h2.y = __float2half_rn(y);
    return *reinterpret_cast<uint32_t*>(&h2);
}

// ---------------------------------------------------------------------------
// Convert all 4 weight matrices fp32->fp16 in one launch.
// ---------------------------------------------------------------------------
__global__ __launch_bounds__(256) void conv_w(const float* __restrict__ w0,
                                              const float* __restrict__ w1,
                                              const float* __restrict__ w2,
                                              const float* __restrict__ w3,
                                              __half* __restrict__ out) {
    int idx = blockIdx.x * 256 + threadIdx.x;      // float4 units
    const int per = DD * DD / 4;                   // 262144
    int wsel = idx / per;
    int off = idx - wsel * per;
    const float* src = (wsel == 0) ? w0 : (wsel == 1) ? w1 : (wsel == 2) ? w2 : w3;
    float4 x = reinterpret_cast<const float4*>(src)[off];
    __half2 a; a.x = __float2half_rn(x.x); a.y = __float2half_rn(x.y);
    __half2 b; b.x = __float2half_rn(x.z); b.y = __float2half_rn(x.w);
    __half2* o = reinterpret_cast<__half2*>(out + (size_t)wsel * DD * DD) + off * 2;
    o[0] = a; o[1] = b;
}

// ---------------------------------------------------------------------------
// QKV GEMM (fused A-side fp32->fp16): grid (8, 32, 3).
// C[m,n] = sum_k A[m,k]*W[n,k];  z selects (query,Wq)->Q etc.
// A loaded fp32 via LDG, converted in regs, STS fp16 (prefetch 1 chunk).
// B (fp16 weights) via cp.async double buffer.
// Epilogue: head layout g_{Q,K,V}s[((b*H+h)*S+s)*64+hd], Q scaled by QMULT.
// ---------------------------------------------------------------------------
#define LDHW 40   // smem row stride in halfwords (80 bytes)

__global__ __launch_bounds__(256) void gemm_qkv(const float* __restrict__ Aq,
                                                const float* __restrict__ Ak,
                                                const float* __restrict__ Av,
                                                const __half* __restrict__ W16,
                                                __half* __restrict__ qs,
                                                __half* __restrict__ ks,
                                                __half* __restrict__ vs) {
    constexpr int NK = DD / 32;   // 32
    __shared__ __align__(16) __half sA[2][128 * LDHW];
    __shared__ __align__(16) __half sB[2][128 * LDHW];

    const int t = threadIdx.x;
    const int lane = t & 31;
    const int wid = t >> 5;
    const int wm = (wid >> 2) * 64;
    const int wn = (wid & 3) * 32;
    const int bm = blockIdx.y * 128;
    const int bn = blockIdx.x * 128;
    const int z = blockIdx.z;

    const float* A32 = (z == 0) ? Aq : (z == 1) ? Ak : Av;
    const __half* Bw = W16 + (size_t)z * DD * DD;
    __half* outp = (z == 0) ? qs : (z == 1) ? ks : vs;
    const float mult = (z == 0) ? QMULT : 1.0f;

    const uint32_t sAb[2] = { smem_u32(&sA[0][0]), smem_u32(&sA[1][0]) };
    const uint32_t sBb[2] = { smem_u32(&sB[0][0]), smem_u32(&sB[1][0]) };

    const int grow = t >> 1;
    const int gseg = t & 1;
    const float* Ag32 = A32 + (size_t)(bm + grow) * DD + gseg * 16;
    const __half* Bg = Bw + (size_t)(bn + grow) * DD + gseg * 16;
    const uint32_t soff = (uint32_t)grow * (LDHW * 2) + gseg * 32;

    float4 fa[4];
    auto ldgA = [&](int kt) {
        const float4* p = reinterpret_cast<const float4*>(Ag32 + kt * 32);
#pragma unroll
        for (int i = 0; i < 4; i++) fa[i] = p[i];
    };
    auto stsA = [&](int buf) {
        uint32_t h[8];
#pragma unroll
        for (int i = 0; i < 4; i++) {
            h[2 * i + 0] = pack_h2(fa[i].x, fa[i].y);
            h[2 * i + 1] = pack_h2(fa[i].z, fa[i].w);
        }
        asm volatile("st.shared.v4.b32 [%0], {%1,%2,%3,%4};"
                     :: "r"(sAb[buf] + soff), "r"(h[0]), "r"(h[1]), "r"(h[2]), "r"(h[3])
                     : "memory");
        asm volatile("st.shared.v4.b32 [%0], {%1,%2,%3,%4};"
                     :: "r"(sAb[buf] + soff + 16), "r"(h[4]), "r"(h[5]), "r"(h[6]), "r"(h[7])
                     : "memory");
    };
    auto ldB = [&](int buf, int kt) {
        const int k0 = kt * 32;
        cp16(sBb[buf] + soff,      Bg + k0);
        cp16(sBb[buf] + soff + 16, Bg + k0 + 8);
        cp_commit();
    };

    const uint32_t aoff = (uint32_t)(wm + (lane & 15)) * (LDHW * 2) + ((lane >> 4) << 4);
    const uint32_t boff = (uint32_t)(wn + (lane & 7) + ((lane >> 4) << 3)) * (LDHW * 2)
                        + (((lane >> 3) & 1) << 4);

    float d[4][4][4];
#pragma unroll
    for (int i = 0; i < 4; i++)
#pragma unroll
        for (int j = 0; j < 4; j++)
#pragma unroll
            for (int r = 0; r < 4; r++) d[i][j][r] = 0.0f;

    // prologue
    ldgA(0);
    ldB(0, 0);
    stsA(0);
    cp_wait<0>(); __syncthreads();

    int cur = 0;
    for (int kt = 0; kt < NK; ++kt) {
        if (kt + 1 < NK) { ldgA(kt + 1); ldB(cur ^ 1, kt + 1); }

        uint32_t a[4][2][4];
        uint32_t b[4][2][2];
#pragma unroll
        for (int mf = 0; mf < 4; mf++)
#pragma unroll
            for (int kf = 0; kf < 2; kf++)
                ldm_x4(a[mf][kf], sAb[cur] + aoff + mf * 16 * (LDHW * 2) + kf * 32);
#pragma unroll
        for (int nf2 = 0; nf2 < 2; nf2++)
#pragma unroll
            for (int kf = 0; kf < 2; kf++) {
                uint32_t r[4];
                ldm_x4(r, sBb[cur] + boff + nf2 * 16 * (LDHW * 2) + kf * 32);
                b[nf2 * 2 + 0][kf][0] = r[0]; b[nf2 * 2 + 0][kf][1] = r[1];
                b[nf2 * 2 + 1][kf][0] = r[2]; b[nf2 * 2 + 1][kf][1] = r[3];
            }
#pragma unroll
        for (int mf = 0; mf < 4; mf++)
#pragma unroll
            for (int nf = 0; nf < 4; nf++) {
                mma16816(d[mf][nf], a[mf][0], b[nf][0]);
                mma16816(d[mf][nf], a[mf][1], b[nf][1]);
            }

        if (kt + 1 < NK) { stsA(cur ^ 1); cp_wait<1>(); }
        __syncthreads();
        cur ^= 1;
    }

    // Epilogue: head-layout fp16
    const int mrow = bm + wm + (lane >> 2);
    const int ncol0 = bn + wn + (lane & 3) * 2;
#pragma unroll
    for (int mf = 0; mf < 4; mf++) {
#pragma unroll
        for (int half = 0; half < 2; half++) {
            const int m = mrow + mf * 16 + half * 8;
            const int b = m >> 11;
            const int s = m & (SS - 1);
#pragma unroll
            for (int nf = 0; nf < 4; nf++) {
                const int n = ncol0 + nf * 8;
                const int h = n >> 6;
                const int hd = n & (HDD - 1);
                __half* base = outp + (((size_t)b * HH + h) * SS + s) * 64 + hd;
                *reinterpret_cast<uint32_t*>(base) =
                    pack_h2(d[mf][nf][half * 2 + 0] * mult,
                            d[mf][nf][half * 2 + 1] * mult);
            }
        }
    }
}

// ---------------------------------------------------------------------------
// Output GEMM: A = fp16 ctx [4096,1024] (cp.async), B = Wo fp16, bias, fp32 out
// ---------------------------------------------------------------------------
__global__ __launch_bounds__(256) void gemm_out(const __half* __restrict__ A16,
                                                const __half* __restrict__ W16,
                                                const float* __restrict__ bias,
                                                float* __restrict__ out) {
    constexpr int NK = DD / 32;   // 32
    __shared__ __align__(16) __half sA[2][128 * LDHW];
    __shared__ __align__(16) __half sB[2][128 * LDHW];

    const int t = threadIdx.x;
    const int lane = t & 31;
    const int wid = t >> 5;
    const int wm = (wid >> 2) * 64;
    const int wn = (wid & 3) * 32;
    const int bm = blockIdx.y * 128;
    const int bn = blockIdx.x * 128;

    const uint32_t sAb[2] = { smem_u32(&sA[0][0]), smem_u32(&sA[1][0]) };
    const uint32_t sBb[2] = { smem_u32(&sB[0][0]), smem_u32(&sB[1][0]) };

    const int grow = t >> 1;
    const int gseg = t & 1;
    const __half* Ag = A16 + (size_t)(bm + grow) * DD + gseg * 16;
    const __half* Bg = W16 + (size_t)(bn + grow) * DD + gseg * 16;
    const uint32_t soff = (uint32_t)grow * (LDHW * 2) + gseg * 32;

    auto load_tile = [&](int buf, int kt) {
        const int k0 = kt * 32;
        cp16(sAb[buf] + soff,      Ag + k0);
        cp16(sAb[buf] + soff + 16, Ag + k0 + 8);
        cp16(sBb[buf] + soff,      Bg + k0);
        cp16(sBb[buf] + soff + 16, Bg + k0 + 8);
        cp_commit();
    };

    const uint32_t aoff = (uint32_t)(wm + (lane & 15)) * (LDHW * 2) + ((lane >> 4) << 4);
    const uint32_t boff = (uint32_t)(wn + (lane & 7) + ((lane >> 4) << 3)) * (LDHW * 2)
                        + (((lane >> 3) & 1) << 4);

    float d[4][4][4];
#pragma unroll
    for (int i = 0; i < 4; i++)
#pragma unroll
        for (int j = 0; j < 4; j++)
#pragma unroll
            for (int r = 0; r < 4; r++) d[i][j][r] = 0.0f;

    load_tile(0, 0);
    int cur = 0;
    for (int kt = 0; kt < NK; ++kt) {
        if (kt + 1 < NK) load_tile(cur ^ 1, kt + 1);
        if (kt + 1 < NK) cp_wait<1>(); else cp_wait<0>();
        __syncthreads();

        uint32_t a[4][2][4];
        uint32_t b[4][2][2];
#pragma unroll
        for (int mf = 0; mf < 4; mf++)
#pragma unroll
            for (int kf = 0; kf < 2; kf++)
                ldm_x4(a[mf][kf], sAb[cur] + aoff + mf * 16 * (LDHW * 2) + kf * 32);
#pragma unroll
        for (int nf2 = 0; nf2 < 2; nf2++)
#pragma unroll
            for (int kf = 0; kf < 2; kf++) {
                uint32_t r[4];
                ldm_x4(r, sBb[cur] + boff + nf2 * 16 * (LDHW * 2) + kf * 32);
                b[nf2 * 2 + 0][kf][0] = r[0]; b[nf2 * 2 + 0][kf][1] = r[1];
                b[nf2 * 2 + 1][kf][0] = r[2]; b[nf2 * 2 + 1][kf][1] = r[3];
            }
#pragma unroll
        for (int mf = 0; mf < 4; mf++)
#pragma unroll
            for (int nf = 0; nf < 4; nf++) {
                mma16816(d[mf][nf], a[mf][0], b[nf][0]);
                mma16816(d[mf][nf], a[mf][1], b[nf][1]);
            }
        __syncthreads();
        cur ^= 1;
    }

    const int mrow = bm + wm + (lane >> 2);
    const int ncol0 = bn + wn + (lane & 3) * 2;
#pragma unroll
    for (int mf = 0; mf < 4; mf++) {
#pragma unroll
        for (int half = 0; half < 2; half++) {
            const int m = mrow + mf * 16 + half * 8;
            float* orow = out + (size_t)m * DD;
#pragma unroll
            for (int nf = 0; nf < 4; nf++) {
                const int n = ncol0 + nf * 8;
                float2 o;
                o.x = d[mf][nf][half * 2 + 0] + bias[n];
                o.y = d[mf][nf][half * 2 + 1] + bias[n + 1];
                *reinterpret_cast<float2*>(orow + n) = o;
            }
        }
    }
}

// ---------------------------------------------------------------------------
// Tensor-core flash attention (fp16 operands, fp32 softmax/accum),
// double-buffered K/V tiles, writes fp16 ctx [B*S, D].
// grid (S/128, B*H), 256 threads (8 warps x 16 q rows).
// ---------------------------------------------------------------------------
#define LDK 72    // K/V/Q smem row stride in halfwords (144B)

__global__ __launch_bounds__(256) void attn_mma() {
    __shared__ __align__(16) __half smem[2 * 2 * 64 * LDK];  // 36,864 B

    const int t = threadIdx.x;
    const int lane = t & 31;
    const int w = t >> 5;
    const int bh = blockIdx.y;
    const int q0 = blockIdx.x * 128;

    const uint32_t sbase = smem_u32(smem);
    // buffer layout: [buf][K|V][64*LDK]
    auto sK = [&](int buf) { return sbase + (uint32_t)(buf * 2 + 0) * (64 * LDK * 2); };
    auto sV = [&](int buf) { return sbase + (uint32_t)(buf * 2 + 1) * (64 * LDK * 2); };

    // ---- stage Q tile (128 rows x 128B) into smem start, grab A-fragments ----
    const __half* Qg = g_Qs + ((size_t)bh * SS + q0) * 64;
#pragma unroll
    for (int i = 0; i < 4; i++) {
        int idx = i * 256 + t;
        int row = idx >> 3, ch = idx & 7;
        cp16(sbase + row * (LDK * 2) + ch * 16, Qg + (size_t)row * 64 + ch * 8);
    }
    cp_commit(); cp_wait<0>();
    __syncthreads();

    uint32_t qa[4][4];
    const uint32_t aoff = (uint32_t)(w * 16 + (lane & 15)) * (LDK * 2) + ((lane >> 4) << 4);
#pragma unroll
    for (int kf = 0; kf < 4; kf++) ldm_x4(qa[kf], sbase + aoff + kf * 32);
    __syncthreads();

    // ---- state ----
    float o[8][4];
#pragma unroll
    for (int f = 0; f < 8; f++)
#pragma unroll
        for (int r = 0; r < 4; r++) o[f][r] = 0.0f;
    float mrow[2] = { -1e30f, -1e30f };
    float lsum[2] = { 0.0f, 0.0f };

    const __half* Kg = g_Ks + (size_t)bh * SS * 64;
    const __half* Vg = g_Vs + (size_t)bh * SS * 64;

    const uint32_t boff = (uint32_t)((lane & 7) + ((lane >> 4) << 3)) * (LDK * 2)
                        + (((lane >> 3) & 1) << 4);
    const uint32_t voff = (uint32_t)(lane & 15) * (LDK * 2) + ((lane >> 4) << 4);

    auto issueKV = [&](int buf, int it) {
        const int k0 = it * 64;
#pragma unroll
        for (int i = 0; i < 2; i++) {
            int idx = i * 256 + t;
            int row = idx >> 3, ch = idx & 7;
            cp16(sK(buf) + row * (LDK * 2) + ch * 16, Kg + ((size_t)(k0 + row)) * 64 + ch * 8);
            cp16(sV(buf) + row * (LDK * 2) + ch * 16, Vg + ((size_t)(k0 + row)) * 64 + ch * 8);
        }
        cp_commit();
    };

    constexpr int NT = SS / 64;   // 32
    issueKV(0, 0);
    int buf = 0;
    for (int it = 0; it < NT; ++it) {
        if (it + 1 < NT) { issueKV(buf ^ 1, it + 1); cp_wait<1>(); }
        else cp_wait<0>();
        __syncthreads();

        // ---- S = Q K^T (log2 domain, QMULT pre-folded) ----
        float s[8][4];
#pragma unroll
        for (int f = 0; f < 8; f++)
#pragma unroll
            for (int r = 0; r < 4; r++) s[f][r] = 0.0f;
#pragma unroll
        for (int kf = 0; kf < 4; kf++) {
#pragma unroll
            for (int nc = 0; nc < 4; nc++) {
                uint32_t bk[4];
                ldm_x4(bk, sK(buf) + boff + nc * 16 * (LDK * 2) + kf * 32);
                mma16816(s[2 * nc],     qa[kf], bk + 0);
                mma16816(s[2 * nc + 1], qa[kf], bk + 2);
            }
        }

        // ---- online softmax ----
        float tm0 = -1e30f, tm1 = -1e30f;
#pragma unroll
        for (int f = 0; f < 8; f++) {
            tm0 = fmaxf(tm0, fmaxf(s[f][0], s[f][1]));
            tm1 = fmaxf(tm1, fmaxf(s[f][2], s[f][3]));
        }
        tm0 = fmaxf(tm0, __shfl_xor_sync(0xffffffffu, tm0, 1));
        tm0 = fmaxf(tm0, __shfl_xor_sync(0xffffffffu, tm0, 2));
        tm1 = fmaxf(tm1, __shfl_xor_sync(0xffffffffu, tm1, 1));
        tm1 = fmaxf(tm1, __shfl_xor_sync(0xffffffffu, tm1, 2));
        const float mn0 = fmaxf(mrow[0], tm0);
        const float mn1 = fmaxf(mrow[1], tm1);
        const float sc0 = ex2f(mrow[0] - mn0);
        const float sc1 = ex2f(mrow[1] - mn1);
        mrow[0] = mn0; mrow[1] = mn1;
        lsum[0] *= sc0; lsum[1] *= sc1;
#pragma unroll
        for (int f = 0; f < 8; f++) {
            o[f][0] *= sc0; o[f][1] *= sc0;
            o[f][2] *= sc1; o[f][3] *= sc1;
        }

        // ---- P = exp2(S - m), pack into A-fragments ----
        uint32_t ph[4][4];
#pragma unroll
        for (int kf = 0; kf < 4; kf++) {
#pragma unroll
            for (int j = 0; j < 2; j++) {
                float* sf = s[2 * kf + j];
                float p0 = ex2f(sf[0] - mn0);
                float p1 = ex2f(sf[1] - mn0);
                float p2 = ex2f(sf[2] - mn1);
                float p3 = ex2f(sf[3] - mn1);
                lsum[0] += p0 + p1;
                lsum[1] += p2 + p3;
                ph[kf][2 * j + 0] = pack_h2(p0, p1);
                ph[kf][2 * j + 1] = pack_h2(p2, p3);
            }
        }

        // ---- O += P V, V via ldmatrix.trans ----
#pragma unroll
        for (int kf = 0; kf < 4; kf++) {
#pragma unroll
            for (int nc = 0; nc < 4; nc++) {
                uint32_t bv[4];
                ldm_x4_t(bv, sV(buf) + voff + kf * 16 * (LDK * 2) + nc * 32);
                mma16816(o[2 * nc],     ph[kf], bv + 0);
                mma16816(o[2 * nc + 1], ph[kf], bv + 2);
            }
        }
        __syncthreads();
        buf ^= 1;
    }

    // ---- finalize & store fp16 ctx [B*S, D] ----
    lsum[0] += __shfl_xor_sync(0xffffffffu, lsum[0], 1);
    lsum[0] += __shfl_xor_sync(0xffffffffu, lsum[0], 2);
    lsum[1] += __shfl_xor_sync(0xffffffffu, lsum[1], 1);
    lsum[1] += __shfl_xor_sync(0xffffffffu, lsum[1], 2);
    const float inv0 = 1.0f / lsum[0];
    const float inv1 = 1.0f / lsum[1];

    const int b = bh >> 4;
    const int h = bh & (HH - 1);
    const int r0 = q0 + w * 16 + (lane >> 2);
    const int col = h * HDD + 2 * (lane & 3);
    __half* O0 = g_ctxh + ((size_t)b * SS + r0) * DD + col;
    __half* O1 = g_ctxh + ((size_t)b * SS + r0 + 8) * DD + col;
#pragma unroll
    for (int f = 0; f < 8; f++) {
        *reinterpret_cast<uint32_t*>(O0 + f * 8) = pack_h2(o[f][0] * inv0, o[f][1] * inv0);
        *reinterpret_cast<uint32_t*>(O1 + f * 8) = pack_h2(o[f][2] * inv1, o[f][3] * inv1);
    }
}

// ---------------------------------------------------------------------------
// Launch
// ---------------------------------------------------------------------------
extern "C" void kernel_launch(void* const* d_in, const int* in_sizes, int n_in,
                              void* d_out, int out_size) {
    const float* query = (const float*)d_in[0];
    const float* key_i = (const float*)d_in[1];
    const float* value = (const float*)d_in[2];
    const float* Wq = (const float*)d_in[3];
    const float* Wk = (const float*)d_in[4];
    const float* Wv = (const float*)d_in[5];
    const float* Wo = (const float*)d_in[6];
    const float* bo = (const float*)d_in[7];
    float* out = (float*)d_out;

    __half *qs, *ks, *vs, *ctxh, *w16;
    cudaGetSymbolAddress((void**)&qs, g_Qs);
    cudaGetSymbolAddress((void**)&ks, g_Ks);
    cudaGetSymbolAddress((void**)&vs, g_Vs);
    cudaGetSymbolAddress((void**)&ctxh, g_ctxh);
    cudaGetSymbolAddress((void**)&w16, g_W16);

    // 1. all weights -> fp16 (one small launch)
    conv_w<<<4 * (DD * DD / 4) / 256, 256>>>(Wq, Wk, Wv, Wo, w16);

    // 2. Q,K,V projections in one launch (fused A conversion)
    dim3 qgrid(DD / 128, MROWS / 128, 3);   // (8, 32, 3)
    gemm_qkv<<<qgrid, 256>>>(query, key_i, value, w16, qs, ks, vs);

    // 3. attention -> fp16 ctx
    dim3 agrid(SS / 128, BB * HH);
    attn_mma<<<agrid, 256>>>();

    // 4. output projection
    dim3 ogrid(DD / 128, MROWS / 128);      // (8, 32)
    gemm_out<<<ogrid, 256>>>(ctxh, w16 + (size_t)3 * DD * DD, bo, out);
}